// round 2
// baseline (speedup 1.0000x reference)
#include <cuda_runtime.h>
#include <math.h>

// Problem constants
#define T_STEPS 256
#define BATCH   64
#define DIN     512
#define HID     1024
#define DH      (DIN + HID)       // 1536
#define NG      (4 * HID)         // 4096
#define M1      (T_STEPS * BATCH) // 16384

#define GRID_P  128               // persistent blocks (<=148 SMs -> co-resident)
#define THR_P   128               // threads per persistent block
#define JPB     8                 // j-units per block (128*8 = 1024)
#define CPB     (JPB * 4)         // 32 gate-columns per block

// -------- device scratch (static; no cudaMalloc allowed) --------------------
__device__ float g_WxT[DIN * NG];                 // [k][n] for gemm_x
__device__ float g_Whp[(size_t)HID * NG];         // persistent-packed: [blk][c][k]
__device__ float g_ball[NG];                      // concatenated bias
__device__ float g_Gx[(size_t)M1 * HID * 4];      // packed [m][j][gate]
__device__ float g_hbuf[2][BATCH * HID];          // double-buffered hidden state
__device__ unsigned g_sync;                       // grid barrier counter

// packed f32x2 FMA (FFMA2): d.lo += a.lo*b.lo ; d.hi += a.hi*b.hi
__device__ __forceinline__ void ffma2(unsigned long long& d,
                                      unsigned long long a,
                                      unsigned long long b) {
    asm("fma.rn.f32x2 %0, %1, %2, %0;" : "+l"(d) : "l"(a), "l"(b));
}
__device__ __forceinline__ float lohi(unsigned long long v) {
    return __uint_as_float((unsigned)v) + __uint_as_float((unsigned)(v >> 32));
}
__device__ __forceinline__ float sigmoidf_(float x) { return 1.0f / (1.0f + expf(-x)); }

// ---------------------------------------------------------------------------
// init: zero h buffers, reset barrier, build concatenated bias
// ---------------------------------------------------------------------------
__global__ void init_kernel(const float* __restrict__ bf, const float* __restrict__ bi,
                            const float* __restrict__ bg, const float* __restrict__ bo) {
    int idx = blockIdx.x * blockDim.x + threadIdx.x;
    if (idx < 2 * BATCH * HID) ((float*)g_hbuf)[idx] = 0.f;
    if (idx < NG) {
        int gate = idx >> 10;
        int j = idx & (HID - 1);
        const float* b = (gate == 0) ? bf : (gate == 1) ? bi : (gate == 2) ? bg : bo;
        g_ball[idx] = b[j];
    }
    if (idx == 0) g_sync = 0u;
}

// ---------------------------------------------------------------------------
// pack: W_all rows -> g_WxT [k][n] (k<512) and g_Whp block-sliced (k>=512)
// ---------------------------------------------------------------------------
__global__ void pack_kernel(const float* __restrict__ Wf, const float* __restrict__ Wi,
                            const float* __restrict__ Wg, const float* __restrict__ Wo) {
    __shared__ float tile[32][33];
    int tx = threadIdx.x, ty = threadIdx.y;
    int k0 = blockIdx.x * 32;   // k in [0,1536)
    int n0 = blockIdx.y * 32;   // n in [0,4096)
    int gate = n0 >> 10;        // 32-tiles never cross gate boundary
    const float* W = (gate == 0) ? Wf : (gate == 1) ? Wi : (gate == 2) ? Wg : Wo;
    int j0 = n0 & (HID - 1);

    tile[ty][tx] = W[(size_t)(j0 + ty) * DH + (k0 + tx)];
    __syncthreads();

    int k = k0 + ty;
    int n = n0 + tx;
    float v = tile[tx][ty];
    if (k < DIN) {
        g_WxT[(size_t)k * NG + n] = v;
    } else {
        int kk = k - DIN;
        int j = n & (HID - 1);
        int g = n >> 10;
        int blk = j >> 3;                   // owning persistent block
        int c = (j & 7) * 4 + g;            // column within block (j_loc, gate)
        g_Whp[((size_t)blk * CPB + c) * HID + kk] = v;
    }
}

// ---------------------------------------------------------------------------
// gemm_x: Gx = X @ WxT + b  -> packed [m][j][gate]
//   M=16384, N=4096, K=512. 64x64 tile, 256 thr, f32x2 via dup-B.
// ---------------------------------------------------------------------------
__global__ void __launch_bounds__(256) gemm_x_kernel(const float* __restrict__ X) {
    __shared__ float As[16][68];     // [k][m]
    __shared__ float Bs2[16][136];   // [k][2n] duplicated

    int tid = threadIdx.x;
    int tx = tid & 15;
    int ty = tid >> 4;
    int n0 = blockIdx.x * 64;
    int m0 = blockIdx.y * 64;

    unsigned long long acc[2][4];    // m-pairs x 4 n
    #pragma unroll
    for (int p = 0; p < 2; p++)
        #pragma unroll
        for (int c = 0; c < 4; c++) acc[p][c] = 0ull;

    int am = tid >> 2;               // 0..63
    int akg = (tid & 3) * 4;         // 0,4,8,12
    int bk = tid >> 4;               // 0..15
    int bn = (tid & 15) * 4;         // 0..60
    int ty4 = ty * 4;
    int tx8 = tx * 8;

    for (int k0 = 0; k0 < DIN; k0 += 16) {
        float4 av = *(const float4*)(X + (size_t)(m0 + am) * DIN + k0 + akg);
        As[akg + 0][am] = av.x; As[akg + 1][am] = av.y;
        As[akg + 2][am] = av.z; As[akg + 3][am] = av.w;

        float4 bv = *(const float4*)(&g_WxT[(size_t)(k0 + bk) * NG + n0 + bn]);
        *(float4*)&Bs2[bk][2 * bn]     = make_float4(bv.x, bv.x, bv.y, bv.y);
        *(float4*)&Bs2[bk][2 * bn + 4] = make_float4(bv.z, bv.z, bv.w, bv.w);
        __syncthreads();

        #pragma unroll
        for (int kk = 0; kk < 16; kk++) {
            ulonglong2 a2  = *(const ulonglong2*)&As[kk][ty4];
            ulonglong2 b01 = *(const ulonglong2*)&Bs2[kk][tx8];
            ulonglong2 b23 = *(const ulonglong2*)&Bs2[kk][tx8 + 4];
            ffma2(acc[0][0], a2.x, b01.x); ffma2(acc[1][0], a2.y, b01.x);
            ffma2(acc[0][1], a2.x, b01.y); ffma2(acc[1][1], a2.y, b01.y);
            ffma2(acc[0][2], a2.x, b23.x); ffma2(acc[1][2], a2.y, b23.x);
            ffma2(acc[0][3], a2.x, b23.y); ffma2(acc[1][3], a2.y, b23.y);
        }
        __syncthreads();
    }

    #pragma unroll
    for (int c = 0; c < 4; c++) {
        int n = n0 + tx * 4 + c;
        int j = n & (HID - 1);
        int gate = n >> 10;
        float bias = g_ball[n];
        #pragma unroll
        for (int p = 0; p < 2; p++) {
            unsigned long long v = acc[p][c];
            int m = m0 + ty4 + p * 2;
            g_Gx[((size_t)m * HID + j) * 4 + gate]       = __uint_as_float((unsigned)v) + bias;
            g_Gx[((size_t)(m + 1) * HID + j) * 4 + gate] = __uint_as_float((unsigned)(v >> 32)) + bias;
        }
    }
}

// ---------------------------------------------------------------------------
// Persistent LSTM recurrence. 128 blocks x 128 threads.
//   Block owns 8 j-units (32 gate cols). Weights in SMEM (128KB, loaded once).
//   Cell state c lives in registers across all 256 steps.
//   Per step: stage h in 4 SMEM chunks, f32x2 GEMM, fused epilogue, grid barrier.
// ---------------------------------------------------------------------------
__global__ void __launch_bounds__(THR_P, 1) lstm_persistent(float* __restrict__ out,
                                                            int write_tail) {
    extern __shared__ float smem[];
    float* sW = smem;                    // [32][1028]  (k-padded)
    float* sH = smem + CPB * 1028;       // [64][260]   (k-chunk 256, padded)

    const int tid = threadIdx.x;
    const int blk = blockIdx.x;
    const int j_loc = tid >> 4;          // 0..7
    const int bt = tid & 15;             // 0..15 (batch strided by 16)
    const int jg = blk * JPB + j_loc;    // global hidden unit

    // load this block's weight slice (contiguous in g_Whp)
    const float* wsrc = &g_Whp[(size_t)blk * CPB * HID];
    for (int i = tid; i < CPB * HID; i += THR_P) {
        int c = i >> 10;
        int k = i & (HID - 1);
        sW[c * 1028 + k] = wsrc[i];
    }
    __syncthreads();

    const float* wp = sW + (j_loc * 4) * 1028;

    float c_reg[4] = {0.f, 0.f, 0.f, 0.f};

    for (int t = 0; t < T_STEPS; t++) {
        const float* hsrc = g_hbuf[t & 1];
        float* hdst = g_hbuf[(t + 1) & 1];

        // prefetch Gx for this step (packed [m][j][gate] -> float4)
        float4 gxv[4];
        #pragma unroll
        for (int rb = 0; rb < 4; rb++) {
            int b = bt + rb * 16;
            gxv[rb] = *(const float4*)&g_Gx[(((size_t)t * BATCH + b) * HID + jg) * 4];
        }

        unsigned long long acc[4][4];
        #pragma unroll
        for (int rb = 0; rb < 4; rb++)
            #pragma unroll
            for (int g = 0; g < 4; g++) acc[rb][g] = 0ull;

        for (int chunk = 0; chunk < 4; chunk++) {
            const int k0 = chunk * 256;
            __syncthreads();
            // stage h[64][k0:k0+256] into sH
            for (int i = tid; i < 64 * 64; i += THR_P) {
                int row = i >> 6;
                int col4 = (i & 63) * 4;
                *(float4*)&sH[row * 260 + col4] =
                    *(const float4*)&hsrc[row * HID + k0 + col4];
            }
            __syncthreads();

            #pragma unroll 4
            for (int k = 0; k < 256; k += 4) {
                const float* wk = wp + k0 + k;
                ulonglong2 w0 = *(const ulonglong2*)(wk);
                ulonglong2 w1 = *(const ulonglong2*)(wk + 1028);
                ulonglong2 w2 = *(const ulonglong2*)(wk + 2056);
                ulonglong2 w3 = *(const ulonglong2*)(wk + 3084);
                #pragma unroll
                for (int rb = 0; rb < 4; rb++) {
                    ulonglong2 hv = *(const ulonglong2*)&sH[(bt + rb * 16) * 260 + k];
                    ffma2(acc[rb][0], hv.x, w0.x); ffma2(acc[rb][0], hv.y, w0.y);
                    ffma2(acc[rb][1], hv.x, w1.x); ffma2(acc[rb][1], hv.y, w1.y);
                    ffma2(acc[rb][2], hv.x, w2.x); ffma2(acc[rb][2], hv.y, w2.y);
                    ffma2(acc[rb][3], hv.x, w3.x); ffma2(acc[rb][3], hv.y, w3.y);
                }
            }
        }

        // fused epilogue
        #pragma unroll
        for (int rb = 0; rb < 4; rb++) {
            int b = bt + rb * 16;
            float vf = gxv[rb].x + lohi(acc[rb][0]);
            float vi = gxv[rb].y + lohi(acc[rb][1]);
            float vg = gxv[rb].z + lohi(acc[rb][2]);
            float vo = gxv[rb].w + lohi(acc[rb][3]);
            vf = sigmoidf_(vf);
            vi = sigmoidf_(vi);
            vg = tanhf(vg);
            vo = sigmoidf_(vo);
            float cc = vf * c_reg[rb] + vi * vg;
            float h = vo * tanhf(cc);
            c_reg[rb] = cc;
            hdst[b * HID + jg] = h;
            out[(size_t)t * (BATCH * HID) + b * HID + jg] = h;
            if (write_tail && t == T_STEPS - 1) {
                out[(size_t)T_STEPS * BATCH * HID + b * HID + jg] = h;
                out[(size_t)T_STEPS * BATCH * HID + BATCH * HID + b * HID + jg] = cc;
            }
        }

        // grid barrier (monotonic counter, reset by init_kernel each replay)
        __threadfence();
        __syncthreads();
        if (tid == 0) {
            atomicAdd(&g_sync, 1u);
            unsigned target = (unsigned)GRID_P * (unsigned)(t + 1);
            while (*(volatile unsigned*)&g_sync < target) { }
            __threadfence();
        }
        __syncthreads();
    }
}

// ---------------------------------------------------------------------------
extern "C" void kernel_launch(void* const* d_in, const int* in_sizes, int n_in,
                              void* d_out, int out_size) {
    const float* X  = (const float*)d_in[0];
    const float* Wf = (const float*)d_in[1];
    const float* bf = (const float*)d_in[2];
    const float* Wi = (const float*)d_in[3];
    const float* bi = (const float*)d_in[4];
    const float* Wg = (const float*)d_in[5];
    const float* bg = (const float*)d_in[6];
    const float* Wo = (const float*)d_in[7];
    const float* bo = (const float*)d_in[8];
    float* out = (float*)d_out;

    const int SMEM_P = (CPB * 1028 + BATCH * 260) * sizeof(float);  // ~198 KB
    cudaFuncSetAttribute(lstm_persistent,
                         cudaFuncAttributeMaxDynamicSharedMemorySize, SMEM_P);

    init_kernel<<<(2 * BATCH * HID + 255) / 256, 256>>>(bf, bi, bg, bo);
    pack_kernel<<<dim3(DH / 32, NG / 32), dim3(32, 32)>>>(Wf, Wi, Wg, Wo);
    gemm_x_kernel<<<dim3(NG / 64, M1 / 64), 256>>>(X);

    const long long OUT_MAIN = (long long)T_STEPS * BATCH * HID;
    int write_tail = ((long long)out_size >= OUT_MAIN + 2LL * BATCH * HID) ? 1 : 0;

    lstm_persistent<<<GRID_P, THR_P, SMEM_P>>>(out, write_tail);
}

// round 5
// speedup vs baseline: 1.6069x; 1.6069x over previous
#include <cuda_runtime.h>
#include <cuda_bf16.h>
#include <math.h>

// Problem constants
#define T_STEPS 256
#define BATCH   64
#define DIN     512
#define HID     1024
#define DH      (DIN + HID)       // 1536
#define NG      (4 * HID)         // 4096
#define M1      (T_STEPS * BATCH) // 16384

#define GRID_P  128               // persistent blocks
#define THR_P   256               // 8 warps
#define JPB     8                 // j-units per block
#define CPB     32                // gate-columns per block

// ---- SMEM layout (bytes) ----------------------------------------------------
// W tiles: [32 c][1032 k] bf16 (pad 8)   -> 66048 each
#define WPAD     1032
#define SM_WHI   0
#define SM_WLO   66048
// A chunk buffers: [128 rows][136 k] bf16 (pad 8) -> 34816 each
#define APAD     136
#define SM_A0    132096
#define SM_A1    166912
#define SMEM_TOTAL 201728
// epilogue exchange D [192 rows][36 cols] f32 (27648 B), aliases SM_A0
#define SM_D     SM_A0
#define DPAD     36

// -------- device scratch -----------------------------------------------------
__device__ float g_WxT[DIN * NG];               // [k][n] for gemm_x
__device__ float g_Whp[(size_t)HID * NG];       // packed [blk][c][k] fp32
__device__ float g_ball[NG];
__device__ float g_Gx[(size_t)M1 * NG];         // [m][j*4+gate], bias folded in
__device__ unsigned short g_hhi[2][BATCH * HID]; // bf16 hi, double buffered
__device__ unsigned short g_hlo[2][BATCH * HID]; // bf16 lo
__device__ unsigned g_sync;

// ---- helpers ------------------------------------------------------------
__device__ __forceinline__ unsigned smem_u32(const void* p) {
    unsigned a;
    asm("{ .reg .u64 t; cvta.to.shared.u64 t, %1; cvt.u32.u64 %0, t; }" : "=r"(a) : "l"(p));
    return a;
}
__device__ __forceinline__ void ldsm4(unsigned* r, unsigned addr) {
    asm volatile("ldmatrix.sync.aligned.m8n8.x4.shared.b16 {%0,%1,%2,%3}, [%4];"
        : "=r"(r[0]), "=r"(r[1]), "=r"(r[2]), "=r"(r[3]) : "r"(addr));
}
__device__ __forceinline__ void mma_bf16(float* d, const unsigned* a, const unsigned* b) {
    asm volatile("mma.sync.aligned.m16n8k16.row.col.f32.bf16.bf16.f32 "
        "{%0,%1,%2,%3}, {%4,%5,%6,%7}, {%8,%9}, {%0,%1,%2,%3};"
        : "+f"(d[0]), "+f"(d[1]), "+f"(d[2]), "+f"(d[3])
        : "r"(a[0]), "r"(a[1]), "r"(a[2]), "r"(a[3]), "r"(b[0]), "r"(b[1]));
}
__device__ __forceinline__ void cp16(unsigned dst, const void* src) {
    asm volatile("cp.async.cg.shared.global [%0], [%1], 16;" :: "r"(dst), "l"(src));
}
#define CP_COMMIT() asm volatile("cp.async.commit_group;" ::: "memory")
#define CP_WAIT0()  asm volatile("cp.async.wait_group 0;" ::: "memory")

// split x,y into bf16 hi pair + bf16 lo pair (lo = x - float(hi))
__device__ __forceinline__ void split2(float x, float y, unsigned& hi, unsigned& lo) {
    unsigned h;
    asm("cvt.rn.bf16x2.f32 %0, %1, %2;" : "=r"(h) : "f"(y), "f"(x));
    float hx = __uint_as_float(h << 16);
    float hy = __uint_as_float(h & 0xffff0000u);
    float lx = x - hx, ly = y - hy;
    asm("cvt.rn.bf16x2.f32 %0, %1, %2;" : "=r"(lo) : "f"(ly), "f"(lx));
    hi = h;
}
__device__ __forceinline__ float sigmoidf_(float x) { return 1.0f / (1.0f + expf(-x)); }

// ---------------------------------------------------------------------------
// init: zero BOTH h double-buffers completely (65536 threads), bias, barrier.
// CRITICAL for graph replay: all cross-call state must be re-initialized.
// ---------------------------------------------------------------------------
__global__ void init_kernel(const float* __restrict__ bf, const float* __restrict__ bi,
                            const float* __restrict__ bg, const float* __restrict__ bo) {
    int idx = blockIdx.x * blockDim.x + threadIdx.x;
    if (idx < BATCH * HID) {
        g_hhi[0][idx] = 0; g_hhi[1][idx] = 0;
        g_hlo[0][idx] = 0; g_hlo[1][idx] = 0;
    }
    if (idx < NG) {
        int gate = idx >> 10;
        int j = idx & (HID - 1);
        const float* b = (gate == 0) ? bf : (gate == 1) ? bi : (gate == 2) ? bg : bo;
        g_ball[idx] = b[j];
    }
    if (idx == 0) g_sync = 0u;
}

__global__ void pack_kernel(const float* __restrict__ Wf, const float* __restrict__ Wi,
                            const float* __restrict__ Wg, const float* __restrict__ Wo) {
    __shared__ float tile[32][33];
    int tx = threadIdx.x, ty = threadIdx.y;
    int k0 = blockIdx.x * 32;
    int n0 = blockIdx.y * 32;
    int gate = n0 >> 10;
    const float* W = (gate == 0) ? Wf : (gate == 1) ? Wi : (gate == 2) ? Wg : Wo;
    int j0 = n0 & (HID - 1);

    tile[ty][tx] = W[(size_t)(j0 + ty) * DH + (k0 + tx)];
    __syncthreads();

    int k = k0 + ty;
    int n = n0 + tx;
    float v = tile[tx][ty];
    if (k < DIN) {
        g_WxT[(size_t)k * NG + n] = v;
    } else {
        int kk = k - DIN;
        int j = n & (HID - 1);
        int g = n >> 10;
        int blk = j >> 3;
        int c = (j & 7) * 4 + g;
        g_Whp[((size_t)blk * CPB + c) * HID + kk] = v;
    }
}

// ---------------------------------------------------------------------------
// gemm_x (fp32 f32x2): Gx = X @ WxT + b  (validated in R2)
// ---------------------------------------------------------------------------
__device__ __forceinline__ void ffma2(unsigned long long& d, unsigned long long a,
                                      unsigned long long b) {
    asm("fma.rn.f32x2 %0, %1, %2, %0;" : "+l"(d) : "l"(a), "l"(b));
}

__global__ void __launch_bounds__(256) gemm_x_kernel(const float* __restrict__ X) {
    __shared__ float As[16][68];
    __shared__ float Bs2[16][136];

    int tid = threadIdx.x;
    int tx = tid & 15;
    int ty = tid >> 4;
    int n0 = blockIdx.x * 64;
    int m0 = blockIdx.y * 64;

    unsigned long long acc[2][4];
    #pragma unroll
    for (int p = 0; p < 2; p++)
        #pragma unroll
        for (int c = 0; c < 4; c++) acc[p][c] = 0ull;

    int am = tid >> 2;
    int akg = (tid & 3) * 4;
    int bk = tid >> 4;
    int bn = (tid & 15) * 4;
    int ty4 = ty * 4;
    int tx8 = tx * 8;

    for (int k0 = 0; k0 < DIN; k0 += 16) {
        float4 av = *(const float4*)(X + (size_t)(m0 + am) * DIN + k0 + akg);
        As[akg + 0][am] = av.x; As[akg + 1][am] = av.y;
        As[akg + 2][am] = av.z; As[akg + 3][am] = av.w;

        float4 bv = *(const float4*)(&g_WxT[(size_t)(k0 + bk) * NG + n0 + bn]);
        *(float4*)&Bs2[bk][2 * bn]     = make_float4(bv.x, bv.x, bv.y, bv.y);
        *(float4*)&Bs2[bk][2 * bn + 4] = make_float4(bv.z, bv.z, bv.w, bv.w);
        __syncthreads();

        #pragma unroll
        for (int kk = 0; kk < 16; kk++) {
            ulonglong2 a2  = *(const ulonglong2*)&As[kk][ty4];
            ulonglong2 b01 = *(const ulonglong2*)&Bs2[kk][tx8];
            ulonglong2 b23 = *(const ulonglong2*)&Bs2[kk][tx8 + 4];
            ffma2(acc[0][0], a2.x, b01.x); ffma2(acc[1][0], a2.y, b01.x);
            ffma2(acc[0][1], a2.x, b01.y); ffma2(acc[1][1], a2.y, b01.y);
            ffma2(acc[0][2], a2.x, b23.x); ffma2(acc[1][2], a2.y, b23.x);
            ffma2(acc[0][3], a2.x, b23.y); ffma2(acc[1][3], a2.y, b23.y);
        }
        __syncthreads();
    }

    #pragma unroll
    for (int c = 0; c < 4; c++) {
        int n = n0 + tx * 4 + c;
        int j = n & (HID - 1);
        int gate = n >> 10;
        float bias = g_ball[n];
        #pragma unroll
        for (int p = 0; p < 2; p++) {
            unsigned long long v = acc[p][c];
            int m = m0 + ty4 + p * 2;
            g_Gx[(size_t)m * NG + j * 4 + gate]       = __uint_as_float((unsigned)v) + bias;
            g_Gx[(size_t)(m + 1) * NG + j * 4 + gate] = __uint_as_float((unsigned)(v >> 32)) + bias;
        }
    }
}

// ---------------------------------------------------------------------------
// Persistent bf16 mma.sync LSTM recurrence. 128 blocks x 256 threads (8 warps).
//   A' = [h_hi ; h_lo] (128 rows), W hi/lo SMEM-resident bf16.
//   preact = hi*Whi + lo*Whi + hi*Wlo (+ Gx).  cp.async double-buffered chunks.
// ---------------------------------------------------------------------------
__global__ void __launch_bounds__(THR_P, 1) lstm_persistent(float* __restrict__ out,
                                                            int write_tail) {
    extern __shared__ char smem[];
    const unsigned sbase = smem_u32(smem);
    const int tid = threadIdx.x;
    const int w   = tid >> 5;
    const int lid = tid & 31;
    const int blk = blockIdx.x;

    // ---- stage weights once: fp32 -> bf16 hi/lo, [c][WPAD] layout ----
    {
        const float* wsrc = g_Whp + (size_t)blk * CPB * HID;
        for (int i4 = tid; i4 < CPB * HID / 4; i4 += THR_P) {
            int c = i4 >> 8;
            int k = (i4 << 2) & 1023;
            float4 v = *(const float4*)(wsrc + ((size_t)c << 10) + k);
            unsigned h01, l01, h23, l23;
            split2(v.x, v.y, h01, l01);
            split2(v.z, v.w, h23, l23);
            unsigned off = (unsigned)(c * WPAD + k) * 2;
            *(uint2*)(smem + SM_WHI + off) = make_uint2(h01, h23);
            *(uint2*)(smem + SM_WLO + off) = make_uint2(l01, l23);
        }
    }
    __syncthreads();

    // per-lane ldmatrix address components (byte offsets)
    const unsigned a1_row = (unsigned)((16 * w + (lid & 15)) * APAD + ((lid >> 4) << 3)) * 2;
    const unsigned a2_row = (unsigned)((16 * (w & 3) + (lid & 15)) * APAD + ((lid >> 4) << 3)) * 2;
    const int c_i   = ((lid >> 4) << 3) + (lid & 7);
    const int khalf = ((lid >> 3) & 1) << 3;
    const unsigned b1_base = sbase + SM_WHI + (unsigned)(c_i * WPAD + khalf) * 2;
    const unsigned b2_base = sbase + SM_WHI + (unsigned)((16 + c_i) * WPAD + khalf) * 2;
    const unsigned b3_base = sbase + SM_WLO + (unsigned)((((w >> 2) << 4) + c_i) * WPAD + khalf) * 2;

    // staging (cp.async) per-thread components
    const int st_row = (tid & 1023) >> 4;        // row within 64
    const int st_c8  = (tid & 15) << 3;          // element col (x8)

    float c_reg[2] = {0.f, 0.f};
    const int b_epi = tid >> 2;
    const int q_epi = tid & 3;
    const long long OUT_MAIN = (long long)T_STEPS * BATCH * HID;

    for (int t = 0; t < T_STEPS; t++) {
        const unsigned short* hhi = g_hhi[t & 1];
        const unsigned short* hlo = g_hlo[t & 1];

        // ---- stage chunk 0 into buf 0 ----
        {
            #pragma unroll
            for (int it = 0; it < 8; it++) {
                int row = ((it & 3) << 4) + st_row;
                const unsigned short* src =
                    ((it >> 2) ? hlo : hhi) + row * HID + 0 * 128 + st_c8;
                unsigned dst = sbase + SM_A0 +
                    (unsigned)((((it >> 2) << 6) + row) * APAD + st_c8) * 2;
                cp16(dst, src);
            }
            CP_COMMIT();
            CP_WAIT0();
            __syncthreads();
        }

        float acc1[4][4], acc2[2][4];
        #pragma unroll
        for (int n = 0; n < 4; n++)
            #pragma unroll
            for (int r = 0; r < 4; r++) acc1[n][r] = 0.f;
        #pragma unroll
        for (int n = 0; n < 2; n++)
            #pragma unroll
            for (int r = 0; r < 4; r++) acc2[n][r] = 0.f;

        for (int ch = 0; ch < 8; ch++) {
            const unsigned abuf = sbase + ((ch & 1) ? SM_A1 : SM_A0);
            // prefetch next chunk into other buffer
            if (ch < 7) {
                const int k0n = (ch + 1) << 7;
                const unsigned dbase = sbase + (((ch + 1) & 1) ? SM_A1 : SM_A0);
                #pragma unroll
                for (int it = 0; it < 8; it++) {
                    int row = ((it & 3) << 4) + st_row;
                    const unsigned short* src =
                        ((it >> 2) ? hlo : hhi) + row * HID + k0n + st_c8;
                    unsigned dst = dbase +
                        (unsigned)((((it >> 2) << 6) + row) * APAD + st_c8) * 2;
                    cp16(dst, src);
                }
                CP_COMMIT();
            }

            // mma over this chunk (8 k-iters of 16)
            #pragma unroll
            for (int kk = 0; kk < 8; kk++) {
                const unsigned akoff = (unsigned)(kk << 5);
                const unsigned wkoff = (unsigned)(((ch << 7) + (kk << 4)) << 1);
                unsigned a1[4], a2[4], b1[4], b2[4], b3[4];
                ldsm4(a1, abuf + a1_row + akoff);
                ldsm4(b1, b1_base + wkoff);
                ldsm4(b2, b2_base + wkoff);
                ldsm4(a2, abuf + a2_row + akoff);
                ldsm4(b3, b3_base + wkoff);
                mma_bf16(acc1[0], a1, b1 + 0);
                mma_bf16(acc1[1], a1, b1 + 2);
                mma_bf16(acc1[2], a1, b2 + 0);
                mma_bf16(acc1[3], a1, b2 + 2);
                mma_bf16(acc2[0], a2, b3 + 0);
                mma_bf16(acc2[1], a2, b3 + 2);
            }

            if (ch < 7) {
                CP_WAIT0();
                __syncthreads();
            }
        }

        // ---- exchange accumulators through SMEM (D region aliases A0) ----
        __syncthreads();
        {
            float* D = (float*)(smem + SM_D);
            int r0 = 16 * w + (lid >> 2);
            int cc = 2 * (lid & 3);
            #pragma unroll
            for (int nt = 0; nt < 4; nt++) {
                int col = 8 * nt + cc;
                *(float2*)&D[r0 * DPAD + col]       = make_float2(acc1[nt][0], acc1[nt][1]);
                *(float2*)&D[(r0 + 8) * DPAD + col] = make_float2(acc1[nt][2], acc1[nt][3]);
            }
            int r2 = 128 + 16 * (w & 3) + (lid >> 2);
            int cb = ((w >> 2) << 4) + cc;
            #pragma unroll
            for (int nt = 0; nt < 2; nt++) {
                int col = cb + 8 * nt;
                *(float2*)&D[r2 * DPAD + col]       = make_float2(acc2[nt][0], acc2[nt][1]);
                *(float2*)&D[(r2 + 8) * DPAD + col] = make_float2(acc2[nt][2], acc2[nt][3]);
            }
        }
        __syncthreads();

        // ---- fused epilogue: thread owns (b, 2 j-units) ----
        {
            const float* D = (const float*)(smem + SM_D);
            const int b = b_epi, q = q_epi;
            const float* gx = g_Gx + ((size_t)t * BATCH + b) * NG + blk * CPB + 8 * q;
            float pre[8];
            #pragma unroll
            for (int u = 0; u < 2; u++) {
                float4 d1 = *(const float4*)&D[b * DPAD + 8 * q + 4 * u];
                float4 d2 = *(const float4*)&D[(64 + b) * DPAD + 8 * q + 4 * u];
                float4 d3 = *(const float4*)&D[(128 + b) * DPAD + 8 * q + 4 * u];
                float4 gv = *(const float4*)(gx + 4 * u);
                pre[4 * u + 0] = d1.x + d2.x + d3.x + gv.x;
                pre[4 * u + 1] = d1.y + d2.y + d3.y + gv.y;
                pre[4 * u + 2] = d1.z + d2.z + d3.z + gv.z;
                pre[4 * u + 3] = d1.w + d2.w + d3.w + gv.w;
            }
            float hout[2];
            #pragma unroll
            for (int u = 0; u < 2; u++) {
                float f = sigmoidf_(pre[4 * u + 0]);
                float i = sigmoidf_(pre[4 * u + 1]);
                float g = tanhf(pre[4 * u + 2]);
                float o = sigmoidf_(pre[4 * u + 3]);
                float cc = f * c_reg[u] + i * g;
                hout[u] = o * tanhf(cc);
                c_reg[u] = cc;
            }
            unsigned hi2, lo2;
            split2(hout[0], hout[1], hi2, lo2);
            int jg0 = blk * JPB + 2 * q;
            int hoff = b * HID + jg0;
            *(unsigned*)&g_hhi[(t + 1) & 1][hoff] = hi2;
            *(unsigned*)&g_hlo[(t + 1) & 1][hoff] = lo2;
            *(float2*)&out[(size_t)t * (BATCH * HID) + hoff] = make_float2(hout[0], hout[1]);
            if (write_tail && t == T_STEPS - 1) {
                *(float2*)&out[OUT_MAIN + hoff] = make_float2(hout[0], hout[1]);
                *(float2*)&out[OUT_MAIN + BATCH * HID + hoff] = make_float2(c_reg[0], c_reg[1]);
            }
        }

        // ---- grid barrier ----
        __threadfence();
        __syncthreads();
        if (tid == 0) {
            atomicAdd(&g_sync, 1u);
            unsigned target = (unsigned)GRID_P * (unsigned)(t + 1);
            while (*(volatile unsigned*)&g_sync < target) { }
            __threadfence();
        }
        __syncthreads();
    }
}

// ---------------------------------------------------------------------------
extern "C" void kernel_launch(void* const* d_in, const int* in_sizes, int n_in,
                              void* d_out, int out_size) {
    const float* X  = (const float*)d_in[0];
    const float* Wf = (const float*)d_in[1];
    const float* bf = (const float*)d_in[2];
    const float* Wi = (const float*)d_in[3];
    const float* bi = (const float*)d_in[4];
    const float* Wg = (const float*)d_in[5];
    const float* bg = (const float*)d_in[6];
    const float* Wo = (const float*)d_in[7];
    const float* bo = (const float*)d_in[8];
    float* out = (float*)d_out;

    cudaFuncSetAttribute(lstm_persistent,
                         cudaFuncAttributeMaxDynamicSharedMemorySize, SMEM_TOTAL);

    // FULL coverage init: BATCH*HID = 65536 threads (256 blocks x 256)
    init_kernel<<<(BATCH * HID + 255) / 256, 256>>>(bf, bi, bg, bo);
    pack_kernel<<<dim3(DH / 32, NG / 32), dim3(32, 32)>>>(Wf, Wi, Wg, Wo);
    gemm_x_kernel<<<dim3(NG / 64, M1 / 64), 256>>>(X);

    const long long OUT_MAIN = (long long)T_STEPS * BATCH * HID;
    int write_tail = ((long long)out_size >= OUT_MAIN + 2LL * BATCH * HID) ? 1 : 0;

    lstm_persistent<<<GRID_P, THR_P, SMEM_TOTAL>>>(out, write_tail);
}

// round 6
// speedup vs baseline: 1.6507x; 1.0273x over previous
#include <cuda_runtime.h>
#include <cuda_bf16.h>
#include <math.h>

// Problem constants
#define T_STEPS 256
#define BATCH   64
#define DIN     512
#define HID     1024
#define DH      (DIN + HID)       // 1536
#define NG      (4 * HID)         // 4096
#define M1      (T_STEPS * BATCH) // 16384

#define GRID_P  128               // persistent blocks
#define THR_P   512               // 16 warps
#define JPB     8                 // j-units per block
#define CPB     32                // gate-columns per block

// ---- SMEM layout (bytes) ----------------------------------------------------
// W tiles: [32 c][1032 k] bf16 (pad 8)   -> 66048 each
#define WPAD     1032
#define SM_WHI   0
#define SM_WLO   66048
// A chunk buffers: [128 rows][136 k] bf16 (pad 8) -> 34816 each
#define APAD     136
#define SM_A0    132096
#define SM_A1    166912
#define SMEM_TOTAL 201728
// epilogue exchange D [384 rows][36 cols] f32 (55296 B), aliases SM_A0+part of A1
#define SM_D     SM_A0
#define DPAD     36

// -------- device scratch -----------------------------------------------------
__device__ float g_WxT[DIN * NG];               // [k][n] for gemm_x
__device__ float g_Whp[(size_t)HID * NG];       // packed [blk][c][k] fp32
__device__ float g_ball[NG];
__device__ float g_Gx[(size_t)M1 * NG];         // [m][j*4+gate], bias folded in
__device__ unsigned short g_hhi[2][BATCH * HID]; // bf16 hi, double buffered
__device__ unsigned short g_hlo[2][BATCH * HID]; // bf16 lo
__device__ unsigned g_sync;

// ---- helpers ------------------------------------------------------------
__device__ __forceinline__ unsigned smem_u32(const void* p) {
    unsigned a;
    asm("{ .reg .u64 t; cvta.to.shared.u64 t, %1; cvt.u32.u64 %0, t; }" : "=r"(a) : "l"(p));
    return a;
}
__device__ __forceinline__ void ldsm4(unsigned* r, unsigned addr) {
    asm volatile("ldmatrix.sync.aligned.m8n8.x4.shared.b16 {%0,%1,%2,%3}, [%4];"
        : "=r"(r[0]), "=r"(r[1]), "=r"(r[2]), "=r"(r[3]) : "r"(addr));
}
__device__ __forceinline__ void mma_bf16(float* d, const unsigned* a, const unsigned* b) {
    asm volatile("mma.sync.aligned.m16n8k16.row.col.f32.bf16.bf16.f32 "
        "{%0,%1,%2,%3}, {%4,%5,%6,%7}, {%8,%9}, {%0,%1,%2,%3};"
        : "+f"(d[0]), "+f"(d[1]), "+f"(d[2]), "+f"(d[3])
        : "r"(a[0]), "r"(a[1]), "r"(a[2]), "r"(a[3]), "r"(b[0]), "r"(b[1]));
}
__device__ __forceinline__ void cp16(unsigned dst, const void* src) {
    asm volatile("cp.async.cg.shared.global [%0], [%1], 16;" :: "r"(dst), "l"(src));
}
#define CP_COMMIT() asm volatile("cp.async.commit_group;" ::: "memory")
#define CP_WAIT0()  asm volatile("cp.async.wait_group 0;" ::: "memory")

// split x,y into bf16 hi pair + bf16 lo pair (lo = x - float(hi))
__device__ __forceinline__ void split2(float x, float y, unsigned& hi, unsigned& lo) {
    unsigned h;
    asm("cvt.rn.bf16x2.f32 %0, %1, %2;" : "=r"(h) : "f"(y), "f"(x));
    float hx = __uint_as_float(h << 16);
    float hy = __uint_as_float(h & 0xffff0000u);
    float lx = x - hx, ly = y - hy;
    asm("cvt.rn.bf16x2.f32 %0, %1, %2;" : "=r"(lo) : "f"(ly), "f"(lx));
    hi = h;
}
__device__ __forceinline__ float sigmoidf_(float x) { return 1.0f / (1.0f + expf(-x)); }

// ---------------------------------------------------------------------------
// init: zero BOTH h double-buffers completely, bias, barrier counter.
// ---------------------------------------------------------------------------
__global__ void init_kernel(const float* __restrict__ bf, const float* __restrict__ bi,
                            const float* __restrict__ bg, const float* __restrict__ bo) {
    int idx = blockIdx.x * blockDim.x + threadIdx.x;
    if (idx < BATCH * HID) {
        g_hhi[0][idx] = 0; g_hhi[1][idx] = 0;
        g_hlo[0][idx] = 0; g_hlo[1][idx] = 0;
    }
    if (idx < NG) {
        int gate = idx >> 10;
        int j = idx & (HID - 1);
        const float* b = (gate == 0) ? bf : (gate == 1) ? bi : (gate == 2) ? bg : bo;
        g_ball[idx] = b[j];
    }
    if (idx == 0) g_sync = 0u;
}

__global__ void pack_kernel(const float* __restrict__ Wf, const float* __restrict__ Wi,
                            const float* __restrict__ Wg, const float* __restrict__ Wo) {
    __shared__ float tile[32][33];
    int tx = threadIdx.x, ty = threadIdx.y;
    int k0 = blockIdx.x * 32;
    int n0 = blockIdx.y * 32;
    int gate = n0 >> 10;
    const float* W = (gate == 0) ? Wf : (gate == 1) ? Wi : (gate == 2) ? Wg : Wo;
    int j0 = n0 & (HID - 1);

    tile[ty][tx] = W[(size_t)(j0 + ty) * DH + (k0 + tx)];
    __syncthreads();

    int k = k0 + ty;
    int n = n0 + tx;
    float v = tile[tx][ty];
    if (k < DIN) {
        g_WxT[(size_t)k * NG + n] = v;
    } else {
        int kk = k - DIN;
        int j = n & (HID - 1);
        int g = n >> 10;
        int blk = j >> 3;
        int c = (j & 7) * 4 + g;
        g_Whp[((size_t)blk * CPB + c) * HID + kk] = v;
    }
}

// ---------------------------------------------------------------------------
// gemm_x (fp32 f32x2): Gx = X @ WxT + b  (validated)
// ---------------------------------------------------------------------------
__device__ __forceinline__ void ffma2(unsigned long long& d, unsigned long long a,
                                      unsigned long long b) {
    asm("fma.rn.f32x2 %0, %1, %2, %0;" : "+l"(d) : "l"(a), "l"(b));
}

__global__ void __launch_bounds__(256) gemm_x_kernel(const float* __restrict__ X) {
    __shared__ float As[16][68];
    __shared__ float Bs2[16][136];

    int tid = threadIdx.x;
    int tx = tid & 15;
    int ty = tid >> 4;
    int n0 = blockIdx.x * 64;
    int m0 = blockIdx.y * 64;

    unsigned long long acc[2][4];
    #pragma unroll
    for (int p = 0; p < 2; p++)
        #pragma unroll
        for (int c = 0; c < 4; c++) acc[p][c] = 0ull;

    int am = tid >> 2;
    int akg = (tid & 3) * 4;
    int bk = tid >> 4;
    int bn = (tid & 15) * 4;
    int ty4 = ty * 4;
    int tx8 = tx * 8;

    for (int k0 = 0; k0 < DIN; k0 += 16) {
        float4 av = *(const float4*)(X + (size_t)(m0 + am) * DIN + k0 + akg);
        As[akg + 0][am] = av.x; As[akg + 1][am] = av.y;
        As[akg + 2][am] = av.z; As[akg + 3][am] = av.w;

        float4 bv = *(const float4*)(&g_WxT[(size_t)(k0 + bk) * NG + n0 + bn]);
        *(float4*)&Bs2[bk][2 * bn]     = make_float4(bv.x, bv.x, bv.y, bv.y);
        *(float4*)&Bs2[bk][2 * bn + 4] = make_float4(bv.z, bv.z, bv.w, bv.w);
        __syncthreads();

        #pragma unroll
        for (int kk = 0; kk < 16; kk++) {
            ulonglong2 a2  = *(const ulonglong2*)&As[kk][ty4];
            ulonglong2 b01 = *(const ulonglong2*)&Bs2[kk][tx8];
            ulonglong2 b23 = *(const ulonglong2*)&Bs2[kk][tx8 + 4];
            ffma2(acc[0][0], a2.x, b01.x); ffma2(acc[1][0], a2.y, b01.x);
            ffma2(acc[0][1], a2.x, b01.y); ffma2(acc[1][1], a2.y, b01.y);
            ffma2(acc[0][2], a2.x, b23.x); ffma2(acc[1][2], a2.y, b23.x);
            ffma2(acc[0][3], a2.x, b23.y); ffma2(acc[1][3], a2.y, b23.y);
        }
        __syncthreads();
    }

    #pragma unroll
    for (int c = 0; c < 4; c++) {
        int n = n0 + tx * 4 + c;
        int j = n & (HID - 1);
        int gate = n >> 10;
        float bias = g_ball[n];
        #pragma unroll
        for (int p = 0; p < 2; p++) {
            unsigned long long v = acc[p][c];
            int m = m0 + ty4 + p * 2;
            g_Gx[(size_t)m * NG + j * 4 + gate]       = __uint_as_float((unsigned)v) + bias;
            g_Gx[(size_t)(m + 1) * NG + j * 4 + gate] = __uint_as_float((unsigned)(v >> 32)) + bias;
        }
    }
}

// ---------------------------------------------------------------------------
// Persistent bf16 mma.sync LSTM recurrence. 128 blocks x 512 threads (16 warps).
//   Two warp groups split each chunk's 8 k16-iters (kh = w>>3 takes kk 0-3 / 4-7),
//   partials summed in the D exchange. Numerics identical to R5.
// ---------------------------------------------------------------------------
__global__ void __launch_bounds__(THR_P, 1) lstm_persistent(float* __restrict__ out,
                                                            int write_tail) {
    extern __shared__ char smem[];
    const unsigned sbase = smem_u32(smem);
    const int tid = threadIdx.x;
    const int w   = tid >> 5;
    const int lid = tid & 31;
    const int kh  = w >> 3;            // k-half group (0: kk 0-3, 1: kk 4-7)
    const int wl  = w & 7;             // role within group
    const int blk = blockIdx.x;

    // ---- stage weights once: fp32 -> bf16 hi/lo, [c][WPAD] layout ----
    {
        const float* wsrc = g_Whp + (size_t)blk * CPB * HID;
        for (int i4 = tid; i4 < CPB * HID / 4; i4 += THR_P) {
            int c = i4 >> 8;
            int k = (i4 << 2) & 1023;
            float4 v = *(const float4*)(wsrc + ((size_t)c << 10) + k);
            unsigned h01, l01, h23, l23;
            split2(v.x, v.y, h01, l01);
            split2(v.z, v.w, h23, l23);
            unsigned off = (unsigned)(c * WPAD + k) * 2;
            *(uint2*)(smem + SM_WHI + off) = make_uint2(h01, h23);
            *(uint2*)(smem + SM_WLO + off) = make_uint2(l01, l23);
        }
    }
    __syncthreads();

    // per-lane ldmatrix address components (byte offsets)
    const unsigned a1_row = (unsigned)((16 * wl + (lid & 15)) * APAD + ((lid >> 4) << 3)) * 2;
    const unsigned a2_row = (unsigned)((16 * (wl & 3) + (lid & 15)) * APAD + ((lid >> 4) << 3)) * 2;
    const int c_i   = ((lid >> 4) << 3) + (lid & 7);
    const int khalf = ((lid >> 3) & 1) << 3;
    const unsigned b1_base = sbase + SM_WHI + (unsigned)(c_i * WPAD + khalf) * 2;
    const unsigned b2_base = sbase + SM_WHI + (unsigned)((16 + c_i) * WPAD + khalf) * 2;
    const unsigned b3_base = sbase + SM_WLO + (unsigned)((((wl >> 2) << 4) + c_i) * WPAD + khalf) * 2;

    // staging (cp.async): 4 iters x 512 threads = 2048 float4 slots per chunk
    // slot = it*512 + tid ; part = slot>>10 (hi/lo); row = (slot>>4)&63; col8 = (slot&15)*8

    float c_state = 0.f;
    const int b_epi = tid >> 3;        // batch row 0..63
    const int q_epi = tid & 7;         // j-unit 0..7
    const long long OUT_MAIN = (long long)T_STEPS * BATCH * HID;

    for (int t = 0; t < T_STEPS; t++) {
        const unsigned short* hhi = g_hhi[t & 1];
        const unsigned short* hlo = g_hlo[t & 1];

        // prefetch Gx for this step (hides DRAM latency under staging+mma)
        const float4 gxv = *(const float4*)&g_Gx[((size_t)t * BATCH + b_epi) * NG
                                                 + blk * CPB + 4 * q_epi];

        // ---- stage chunk 0 into buf 0 ----
        {
            #pragma unroll
            for (int it = 0; it < 4; it++) {
                int slot = it * THR_P + tid;
                int part = slot >> 10;
                int row = (slot >> 4) & 63;
                int c8 = (slot & 15) << 3;
                const unsigned short* src = (part ? hlo : hhi) + row * HID + c8;
                unsigned dst = sbase + SM_A0 +
                    (unsigned)(((part << 6) + row) * APAD + c8) * 2;
                cp16(dst, src);
            }
            CP_COMMIT();
            CP_WAIT0();
            __syncthreads();
        }

        float acc1[4][4], acc2[2][4];
        #pragma unroll
        for (int n = 0; n < 4; n++)
            #pragma unroll
            for (int r = 0; r < 4; r++) acc1[n][r] = 0.f;
        #pragma unroll
        for (int n = 0; n < 2; n++)
            #pragma unroll
            for (int r = 0; r < 4; r++) acc2[n][r] = 0.f;

        for (int ch = 0; ch < 8; ch++) {
            const unsigned abuf = sbase + ((ch & 1) ? SM_A1 : SM_A0);
            // prefetch next chunk into other buffer
            if (ch < 7) {
                const int k0n = (ch + 1) << 7;
                const unsigned dbase = sbase + (((ch + 1) & 1) ? SM_A1 : SM_A0);
                #pragma unroll
                for (int it = 0; it < 4; it++) {
                    int slot = it * THR_P + tid;
                    int part = slot >> 10;
                    int row = (slot >> 4) & 63;
                    int c8 = (slot & 15) << 3;
                    const unsigned short* src = (part ? hlo : hhi) + row * HID + k0n + c8;
                    unsigned dst = dbase +
                        (unsigned)(((part << 6) + row) * APAD + c8) * 2;
                    cp16(dst, src);
                }
                CP_COMMIT();
            }

            // mma over this warp-group's 4 k16-iters of the chunk
            #pragma unroll
            for (int kkl = 0; kkl < 4; kkl++) {
                const int kk = (kh << 2) + kkl;
                const unsigned akoff = (unsigned)(kk << 5);
                const unsigned wkoff = (unsigned)(((ch << 7) + (kk << 4)) << 1);
                unsigned a1[4], a2[4], b1[4], b2[4], b3[4];
                ldsm4(a1, abuf + a1_row + akoff);
                ldsm4(b1, b1_base + wkoff);
                ldsm4(b2, b2_base + wkoff);
                ldsm4(a2, abuf + a2_row + akoff);
                ldsm4(b3, b3_base + wkoff);
                mma_bf16(acc1[0], a1, b1 + 0);
                mma_bf16(acc1[1], a1, b1 + 2);
                mma_bf16(acc1[2], a1, b2 + 0);
                mma_bf16(acc1[3], a1, b2 + 2);
                mma_bf16(acc2[0], a2, b3 + 0);
                mma_bf16(acc2[1], a2, b3 + 2);
            }

            if (ch < 7) {
                CP_WAIT0();
                __syncthreads();
            }
        }

        // ---- exchange accumulators through SMEM (D region aliases A bufs) ----
        // layout: rows [0,128) acc1 kh=0 | [128,256) acc1 kh=1
        //         rows [256,320) acc2 kh=0 | [320,384) acc2 kh=1
        __syncthreads();
        {
            float* D = (float*)(smem + SM_D);
            int r0 = (kh << 7) + 16 * wl + (lid >> 2);
            int cc = 2 * (lid & 3);
            #pragma unroll
            for (int nt = 0; nt < 4; nt++) {
                int col = 8 * nt + cc;
                *(float2*)&D[r0 * DPAD + col]       = make_float2(acc1[nt][0], acc1[nt][1]);
                *(float2*)&D[(r0 + 8) * DPAD + col] = make_float2(acc1[nt][2], acc1[nt][3]);
            }
            int r2 = 256 + (kh << 6) + 16 * (wl & 3) + (lid >> 2);
            int cb = ((wl >> 2) << 4) + cc;
            #pragma unroll
            for (int nt = 0; nt < 2; nt++) {
                int col = cb + 8 * nt;
                *(float2*)&D[r2 * DPAD + col]       = make_float2(acc2[nt][0], acc2[nt][1]);
                *(float2*)&D[(r2 + 8) * DPAD + col] = make_float2(acc2[nt][2], acc2[nt][3]);
            }
        }
        __syncthreads();

        // ---- fused epilogue: thread owns (b, 1 j-unit) ----
        {
            const float* D = (const float*)(smem + SM_D);
            const int b = b_epi;
            const int c0 = 4 * q_epi;
            // acc1: hi rows {b, 128+b}, lo rows {64+b, 192+b}; acc2: {256+b, 320+b}
            float4 d0 = *(const float4*)&D[b * DPAD + c0];
            float4 d1 = *(const float4*)&D[(128 + b) * DPAD + c0];
            float4 d2 = *(const float4*)&D[(64 + b) * DPAD + c0];
            float4 d3 = *(const float4*)&D[(192 + b) * DPAD + c0];
            float4 d4 = *(const float4*)&D[(256 + b) * DPAD + c0];
            float4 d5 = *(const float4*)&D[(320 + b) * DPAD + c0];
            float pf = d0.x + d1.x + d2.x + d3.x + d4.x + d5.x + gxv.x;
            float pi = d0.y + d1.y + d2.y + d3.y + d4.y + d5.y + gxv.y;
            float pg = d0.z + d1.z + d2.z + d3.z + d4.z + d5.z + gxv.z;
            float po = d0.w + d1.w + d2.w + d3.w + d4.w + d5.w + gxv.w;

            float f = sigmoidf_(pf);
            float i = sigmoidf_(pi);
            float g = tanhf(pg);
            float o = sigmoidf_(po);
            float cc = f * c_state + i * g;
            float h = o * tanhf(cc);
            c_state = cc;

            __nv_bfloat16 hb = __float2bfloat16(h);
            float hf = __bfloat162float(hb);
            __nv_bfloat16 lb = __float2bfloat16(h - hf);

            int jg = blk * JPB + q_epi;
            int hoff = b * HID + jg;
            g_hhi[(t + 1) & 1][hoff] = *(unsigned short*)&hb;
            g_hlo[(t + 1) & 1][hoff] = *(unsigned short*)&lb;
            out[(size_t)t * (BATCH * HID) + hoff] = h;
            if (write_tail && t == T_STEPS - 1) {
                out[OUT_MAIN + hoff] = h;
                out[OUT_MAIN + BATCH * HID + hoff] = cc;
            }
        }

        // ---- grid barrier ----
        __threadfence();
        __syncthreads();
        if (tid == 0) {
            atomicAdd(&g_sync, 1u);
            unsigned target = (unsigned)GRID_P * (unsigned)(t + 1);
            while (*(volatile unsigned*)&g_sync < target) { }
            __threadfence();
        }
        __syncthreads();
    }
}

// ---------------------------------------------------------------------------
extern "C" void kernel_launch(void* const* d_in, const int* in_sizes, int n_in,
                              void* d_out, int out_size) {
    const float* X  = (const float*)d_in[0];
    const float* Wf = (const float*)d_in[1];
    const float* bf = (const float*)d_in[2];
    const float* Wi = (const float*)d_in[3];
    const float* bi = (const float*)d_in[4];
    const float* Wg = (const float*)d_in[5];
    const float* bg = (const float*)d_in[6];
    const float* Wo = (const float*)d_in[7];
    const float* bo = (const float*)d_in[8];
    float* out = (float*)d_out;

    cudaFuncSetAttribute(lstm_persistent,
                         cudaFuncAttributeMaxDynamicSharedMemorySize, SMEM_TOTAL);

    // FULL coverage init: BATCH*HID = 65536 threads
    init_kernel<<<(BATCH * HID + 255) / 256, 256>>>(bf, bi, bg, bo);
    pack_kernel<<<dim3(DH / 32, NG / 32), dim3(32, 32)>>>(Wf, Wi, Wg, Wo);
    gemm_x_kernel<<<dim3(NG / 64, M1 / 64), 256>>>(X);

    const long long OUT_MAIN = (long long)T_STEPS * BATCH * HID;
    int write_tail = ((long long)out_size >= OUT_MAIN + 2LL * BATCH * HID) ? 1 : 0;

    lstm_persistent<<<GRID_P, THR_P, SMEM_TOTAL>>>(out, write_tail);
}

// round 7
// speedup vs baseline: 3.2079x; 1.9433x over previous
#include <cuda_runtime.h>
#include <cuda_bf16.h>
#include <math.h>

// Problem constants
#define T_STEPS 256
#define BATCH   64
#define DIN     512
#define HID     1024
#define DH      (DIN + HID)       // 1536
#define NG      (4 * HID)         // 4096
#define M1      (T_STEPS * BATCH) // 16384

#define GRID_P  128               // persistent blocks
#define THR_P   512               // 16 warps
#define JPB     8                 // j-units per block
#define CPB     32                // gate-columns per block

// ---- LSTM SMEM layout (bytes) ------------------------------------------------
#define WPAD     1032
#define SM_WHI   0
#define SM_WLO   66048
#define APAD     136
#define SM_A0    132096
#define SM_A1    166912
#define SMEM_TOTAL 201728
#define SM_D     SM_A0
#define DPAD     36

// ---- gemm_x_mma SMEM layout (bf16 elems stride) -------------------------------
#define GX_RS    72                 // row stride in bf16 elems (64 + 8 pad)
#define GX_AHI   0
#define GX_ALO   18432              // 128*72*2
#define GX_BHI   36864
#define GX_BLO   46080              // + 64*72*2
#define GX_BUF   55296
#define GX_SMEM  110592             // double buffered

// -------- device scratch -----------------------------------------------------
__device__ float g_Whp[(size_t)HID * NG];        // packed [blk][c][k] fp32 (recurrence)
__device__ float g_ball[NG];
__device__ float g_Gx[(size_t)M1 * NG];          // [m][j*4+gate], bias folded in
__device__ unsigned short g_Xhi[(size_t)M1 * DIN];   // bf16 X hi
__device__ unsigned short g_Xlo[(size_t)M1 * DIN];   // bf16 X lo
__device__ unsigned short g_Wxhi[(size_t)NG * DIN];  // bf16 Wx hi  [n][k]
__device__ unsigned short g_Wxlo[(size_t)NG * DIN];  // bf16 Wx lo  [n][k]
__device__ unsigned short g_hhi[2][BATCH * HID];
__device__ unsigned short g_hlo[2][BATCH * HID];
__device__ unsigned g_sync;

// ---- helpers ------------------------------------------------------------
__device__ __forceinline__ unsigned smem_u32(const void* p) {
    unsigned a;
    asm("{ .reg .u64 t; cvta.to.shared.u64 t, %1; cvt.u32.u64 %0, t; }" : "=r"(a) : "l"(p));
    return a;
}
__device__ __forceinline__ void ldsm4(unsigned* r, unsigned addr) {
    asm volatile("ldmatrix.sync.aligned.m8n8.x4.shared.b16 {%0,%1,%2,%3}, [%4];"
        : "=r"(r[0]), "=r"(r[1]), "=r"(r[2]), "=r"(r[3]) : "r"(addr));
}
__device__ __forceinline__ void mma_bf16(float* d, const unsigned* a, const unsigned* b) {
    asm volatile("mma.sync.aligned.m16n8k16.row.col.f32.bf16.bf16.f32 "
        "{%0,%1,%2,%3}, {%4,%5,%6,%7}, {%8,%9}, {%0,%1,%2,%3};"
        : "+f"(d[0]), "+f"(d[1]), "+f"(d[2]), "+f"(d[3])
        : "r"(a[0]), "r"(a[1]), "r"(a[2]), "r"(a[3]), "r"(b[0]), "r"(b[1]));
}
__device__ __forceinline__ void cp16(unsigned dst, const void* src) {
    asm volatile("cp.async.cg.shared.global [%0], [%1], 16;" :: "r"(dst), "l"(src));
}
#define CP_COMMIT() asm volatile("cp.async.commit_group;" ::: "memory")
#define CP_WAIT0()  asm volatile("cp.async.wait_group 0;" ::: "memory")

__device__ __forceinline__ void split2(float x, float y, unsigned& hi, unsigned& lo) {
    unsigned h;
    asm("cvt.rn.bf16x2.f32 %0, %1, %2;" : "=r"(h) : "f"(y), "f"(x));
    float hx = __uint_as_float(h << 16);
    float hy = __uint_as_float(h & 0xffff0000u);
    float lx = x - hx, ly = y - hy;
    asm("cvt.rn.bf16x2.f32 %0, %1, %2;" : "=r"(lo) : "f"(ly), "f"(lx));
    hi = h;
}
__device__ __forceinline__ float sigmoidf_(float x) { return 1.0f / (1.0f + expf(-x)); }

// ---------------------------------------------------------------------------
// init: zero h double-buffers, bias, barrier counter.
// ---------------------------------------------------------------------------
__global__ void init_kernel(const float* __restrict__ bf, const float* __restrict__ bi,
                            const float* __restrict__ bg, const float* __restrict__ bo) {
    int idx = blockIdx.x * blockDim.x + threadIdx.x;
    if (idx < BATCH * HID) {
        g_hhi[0][idx] = 0; g_hhi[1][idx] = 0;
        g_hlo[0][idx] = 0; g_hlo[1][idx] = 0;
    }
    if (idx < NG) {
        int gate = idx >> 10;
        int j = idx & (HID - 1);
        const float* b = (gate == 0) ? bf : (gate == 1) ? bi : (gate == 2) ? bg : bo;
        g_ball[idx] = b[j];
    }
    if (idx == 0) g_sync = 0u;
}

// pack Wh (k in [512,1536)) -> g_Whp [blk][c][k] fp32 for the recurrence
__global__ void pack_kernel(const float* __restrict__ Wf, const float* __restrict__ Wi,
                            const float* __restrict__ Wg, const float* __restrict__ Wo) {
    __shared__ float tile[32][33];
    int tx = threadIdx.x, ty = threadIdx.y;
    int k0 = DIN + blockIdx.x * 32;   // k in [512,1536)
    int n0 = blockIdx.y * 32;
    int gate = n0 >> 10;
    const float* W = (gate == 0) ? Wf : (gate == 1) ? Wi : (gate == 2) ? Wg : Wo;
    int j0 = n0 & (HID - 1);

    tile[ty][tx] = W[(size_t)(j0 + ty) * DH + (k0 + tx)];
    __syncthreads();

    int k = k0 + ty;
    int n = n0 + tx;
    float v = tile[tx][ty];
    int kk = k - DIN;
    int j = n & (HID - 1);
    int g = n >> 10;
    int blk = j >> 3;
    int c = (j & 7) * 4 + g;
    g_Whp[((size_t)blk * CPB + c) * HID + kk] = v;
}

// Wx (k < 512) -> bf16 hi/lo [n][k], coalesced (no transpose needed)
__global__ void wxpack_kernel(const float* __restrict__ Wf, const float* __restrict__ Wi,
                              const float* __restrict__ Wg, const float* __restrict__ Wo) {
    int i4 = blockIdx.x * blockDim.x + threadIdx.x;  // per 4 elems of [4096][512]
    if (i4 >= NG * DIN / 4) return;
    int n = i4 >> 7;
    int k = (i4 & 127) << 2;
    int gate = n >> 10;
    int j = n & (HID - 1);
    const float* W = (gate == 0) ? Wf : (gate == 1) ? Wi : (gate == 2) ? Wg : Wo;
    float4 v = *(const float4*)(W + (size_t)j * DH + k);
    unsigned h01, l01, h23, l23;
    split2(v.x, v.y, h01, l01);
    split2(v.z, v.w, h23, l23);
    *(uint2*)&g_Wxhi[(size_t)n * DIN + k] = make_uint2(h01, h23);
    *(uint2*)&g_Wxlo[(size_t)n * DIN + k] = make_uint2(l01, l23);
}

// X -> bf16 hi/lo
__global__ void xsplit_kernel(const float* __restrict__ X) {
    int i4 = blockIdx.x * blockDim.x + threadIdx.x;  // per 4 elems
    if (i4 >= M1 * DIN / 4) return;
    size_t e = (size_t)i4 << 2;
    float4 v = *(const float4*)(X + e);
    unsigned h01, l01, h23, l23;
    split2(v.x, v.y, h01, l01);
    split2(v.z, v.w, h23, l23);
    *(uint2*)&g_Xhi[e] = make_uint2(h01, h23);
    *(uint2*)&g_Xlo[e] = make_uint2(l01, l23);
}

// ---------------------------------------------------------------------------
// gemm_x_mma: Gx = X @ WxT + b  via bf16 mma.sync, full 4-product split.
//   Block: 128 m x 64 n, 8 warps (warp = 16 m-rows x 64 n), K chunks of 64,
//   cp.async double-buffered. acc += Xhi*Whi + Xlo*Whi + Xhi*Wlo + Xlo*Wlo.
// ---------------------------------------------------------------------------
__global__ void __launch_bounds__(256) gemm_x_mma(int dummy) {
    extern __shared__ char smem[];
    const unsigned sbase = smem_u32(smem);
    const int tid = threadIdx.x;
    const int w   = tid >> 5;
    const int lid = tid & 31;
    const int n0  = blockIdx.x * 64;
    const int m0  = blockIdx.y * 128;
    const int gate = n0 >> 10;
    const int jb   = n0 & (HID - 1);

    // ldsm per-lane offsets (bytes); row stride = GX_RS*2 = 144
    const unsigned a_off = (unsigned)((16 * w + (lid & 15)) * GX_RS + ((lid >> 4) << 3)) * 2;
    const unsigned b_off = (unsigned)((((lid >> 4) << 3) | (lid & 7)) * GX_RS
                                      + (((lid >> 3) & 1) << 3)) * 2;

    float acc[8][4];
    #pragma unroll
    for (int nt = 0; nt < 8; nt++)
        #pragma unroll
        for (int r = 0; r < 4; r++) acc[nt][r] = 0.f;

    // staging mapping: 12 cp16/thread per chunk
    //   it 0-3: Ahi (slots 0-1023), it 4-7: Alo, it 8-9: Bhi, it 10-11: Blo
    const int st_c8 = (tid & 7) << 3;       // k-col elems within chunk (x8)

    // ---- stage chunk 0 ----
    {
        const int k0 = 0;
        #pragma unroll
        for (int it = 0; it < 4; it++) {
            int row = (it << 5) + (tid >> 3);
            cp16(sbase + GX_AHI + (unsigned)(row * GX_RS + st_c8) * 2,
                 g_Xhi + (size_t)(m0 + row) * DIN + k0 + st_c8);
            cp16(sbase + GX_ALO + (unsigned)(row * GX_RS + st_c8) * 2,
                 g_Xlo + (size_t)(m0 + row) * DIN + k0 + st_c8);
        }
        #pragma unroll
        for (int it = 0; it < 2; it++) {
            int row = (it << 5) + (tid >> 3);
            cp16(sbase + GX_BHI + (unsigned)(row * GX_RS + st_c8) * 2,
                 g_Wxhi + (size_t)(n0 + row) * DIN + k0 + st_c8);
            cp16(sbase + GX_BLO + (unsigned)(row * GX_RS + st_c8) * 2,
                 g_Wxlo + (size_t)(n0 + row) * DIN + k0 + st_c8);
        }
        CP_COMMIT();
        CP_WAIT0();
        __syncthreads();
    }

    for (int ch = 0; ch < 8; ch++) {
        const unsigned buf = sbase + (ch & 1) * GX_BUF;
        // prefetch next chunk
        if (ch < 7) {
            const int k0 = (ch + 1) << 6;
            const unsigned dbuf = sbase + ((ch + 1) & 1) * GX_BUF;
            #pragma unroll
            for (int it = 0; it < 4; it++) {
                int row = (it << 5) + (tid >> 3);
                cp16(dbuf + GX_AHI + (unsigned)(row * GX_RS + st_c8) * 2,
                     g_Xhi + (size_t)(m0 + row) * DIN + k0 + st_c8);
                cp16(dbuf + GX_ALO + (unsigned)(row * GX_RS + st_c8) * 2,
                     g_Xlo + (size_t)(m0 + row) * DIN + k0 + st_c8);
            }
            #pragma unroll
            for (int it = 0; it < 2; it++) {
                int row = (it << 5) + (tid >> 3);
                cp16(dbuf + GX_BHI + (unsigned)(row * GX_RS + st_c8) * 2,
                     g_Wxhi + (size_t)(n0 + row) * DIN + k0 + st_c8);
                cp16(dbuf + GX_BLO + (unsigned)(row * GX_RS + st_c8) * 2,
                     g_Wxlo + (size_t)(n0 + row) * DIN + k0 + st_c8);
            }
            CP_COMMIT();
        }

        #pragma unroll
        for (int kk = 0; kk < 4; kk++) {
            const unsigned ko = (unsigned)(kk << 5);   // 16 elems * 2B
            unsigned ahi[4], alo[4];
            ldsm4(ahi, buf + GX_AHI + a_off + ko);
            ldsm4(alo, buf + GX_ALO + a_off + ko);
            #pragma unroll
            for (int s = 0; s < 4; s++) {
                const unsigned so = (unsigned)(s * 16 * GX_RS * 2);
                unsigned bhi[4], blo[4];
                ldsm4(bhi, buf + GX_BHI + b_off + so + ko);
                ldsm4(blo, buf + GX_BLO + b_off + so + ko);
                mma_bf16(acc[2 * s],     ahi, bhi + 0);
                mma_bf16(acc[2 * s],     alo, bhi + 0);
                mma_bf16(acc[2 * s],     ahi, blo + 0);
                mma_bf16(acc[2 * s],     alo, blo + 0);
                mma_bf16(acc[2 * s + 1], ahi, bhi + 2);
                mma_bf16(acc[2 * s + 1], alo, bhi + 2);
                mma_bf16(acc[2 * s + 1], ahi, blo + 2);
                mma_bf16(acc[2 * s + 1], alo, blo + 2);
            }
        }

        if (ch < 7) {
            CP_WAIT0();
            __syncthreads();
        }
    }

    // ---- epilogue: write packed g_Gx[m][j*4+gate] + bias ----
    const int r0 = m0 + 16 * w + (lid >> 2);
    #pragma unroll
    for (int nt = 0; nt < 8; nt++) {
        int jc = jb + nt * 8 + (lid & 3) * 2;
        float b0 = g_ball[(gate << 10) + jc];
        float b1 = g_ball[(gate << 10) + jc + 1];
        g_Gx[(size_t)r0 * NG + jc * 4 + gate]           = acc[nt][0] + b0;
        g_Gx[(size_t)r0 * NG + (jc + 1) * 4 + gate]     = acc[nt][1] + b1;
        g_Gx[(size_t)(r0 + 8) * NG + jc * 4 + gate]     = acc[nt][2] + b0;
        g_Gx[(size_t)(r0 + 8) * NG + (jc + 1) * 4 + gate] = acc[nt][3] + b1;
    }
}

// ---------------------------------------------------------------------------
// Persistent bf16 mma.sync LSTM recurrence (validated R6, unchanged).
// ---------------------------------------------------------------------------
__global__ void __launch_bounds__(THR_P, 1) lstm_persistent(float* __restrict__ out,
                                                            int write_tail) {
    extern __shared__ char smem[];
    const unsigned sbase = smem_u32(smem);
    const int tid = threadIdx.x;
    const int w   = tid >> 5;
    const int lid = tid & 31;
    const int kh  = w >> 3;
    const int wl  = w & 7;
    const int blk = blockIdx.x;

    {
        const float* wsrc = g_Whp + (size_t)blk * CPB * HID;
        for (int i4 = tid; i4 < CPB * HID / 4; i4 += THR_P) {
            int c = i4 >> 8;
            int k = (i4 << 2) & 1023;
            float4 v = *(const float4*)(wsrc + ((size_t)c << 10) + k);
            unsigned h01, l01, h23, l23;
            split2(v.x, v.y, h01, l01);
            split2(v.z, v.w, h23, l23);
            unsigned off = (unsigned)(c * WPAD + k) * 2;
            *(uint2*)(smem + SM_WHI + off) = make_uint2(h01, h23);
            *(uint2*)(smem + SM_WLO + off) = make_uint2(l01, l23);
        }
    }
    __syncthreads();

    const unsigned a1_row = (unsigned)((16 * wl + (lid & 15)) * APAD + ((lid >> 4) << 3)) * 2;
    const unsigned a2_row = (unsigned)((16 * (wl & 3) + (lid & 15)) * APAD + ((lid >> 4) << 3)) * 2;
    const int c_i   = ((lid >> 4) << 3) + (lid & 7);
    const int khalf = ((lid >> 3) & 1) << 3;
    const unsigned b1_base = sbase + SM_WHI + (unsigned)(c_i * WPAD + khalf) * 2;
    const unsigned b2_base = sbase + SM_WHI + (unsigned)((16 + c_i) * WPAD + khalf) * 2;
    const unsigned b3_base = sbase + SM_WLO + (unsigned)((((wl >> 2) << 4) + c_i) * WPAD + khalf) * 2;

    float c_state = 0.f;
    const int b_epi = tid >> 3;
    const int q_epi = tid & 7;
    const long long OUT_MAIN = (long long)T_STEPS * BATCH * HID;

    for (int t = 0; t < T_STEPS; t++) {
        const unsigned short* hhi = g_hhi[t & 1];
        const unsigned short* hlo = g_hlo[t & 1];

        const float4 gxv = *(const float4*)&g_Gx[((size_t)t * BATCH + b_epi) * NG
                                                 + blk * CPB + 4 * q_epi];

        {
            #pragma unroll
            for (int it = 0; it < 4; it++) {
                int slot = it * THR_P + tid;
                int part = slot >> 10;
                int row = (slot >> 4) & 63;
                int c8 = (slot & 15) << 3;
                const unsigned short* src = (part ? hlo : hhi) + row * HID + c8;
                unsigned dst = sbase + SM_A0 +
                    (unsigned)(((part << 6) + row) * APAD + c8) * 2;
                cp16(dst, src);
            }
            CP_COMMIT();
            CP_WAIT0();
            __syncthreads();
        }

        float acc1[4][4], acc2[2][4];
        #pragma unroll
        for (int n = 0; n < 4; n++)
            #pragma unroll
            for (int r = 0; r < 4; r++) acc1[n][r] = 0.f;
        #pragma unroll
        for (int n = 0; n < 2; n++)
            #pragma unroll
            for (int r = 0; r < 4; r++) acc2[n][r] = 0.f;

        for (int ch = 0; ch < 8; ch++) {
            const unsigned abuf = sbase + ((ch & 1) ? SM_A1 : SM_A0);
            if (ch < 7) {
                const int k0n = (ch + 1) << 7;
                const unsigned dbase = sbase + (((ch + 1) & 1) ? SM_A1 : SM_A0);
                #pragma unroll
                for (int it = 0; it < 4; it++) {
                    int slot = it * THR_P + tid;
                    int part = slot >> 10;
                    int row = (slot >> 4) & 63;
                    int c8 = (slot & 15) << 3;
                    const unsigned short* src = (part ? hlo : hhi) + row * HID + k0n + c8;
                    unsigned dst = dbase +
                        (unsigned)(((part << 6) + row) * APAD + c8) * 2;
                    cp16(dst, src);
                }
                CP_COMMIT();
            }

            #pragma unroll
            for (int kkl = 0; kkl < 4; kkl++) {
                const int kk = (kh << 2) + kkl;
                const unsigned akoff = (unsigned)(kk << 5);
                const unsigned wkoff = (unsigned)(((ch << 7) + (kk << 4)) << 1);
                unsigned a1[4], a2[4], b1[4], b2[4], b3[4];
                ldsm4(a1, abuf + a1_row + akoff);
                ldsm4(b1, b1_base + wkoff);
                ldsm4(b2, b2_base + wkoff);
                ldsm4(a2, abuf + a2_row + akoff);
                ldsm4(b3, b3_base + wkoff);
                mma_bf16(acc1[0], a1, b1 + 0);
                mma_bf16(acc1[1], a1, b1 + 2);
                mma_bf16(acc1[2], a1, b2 + 0);
                mma_bf16(acc1[3], a1, b2 + 2);
                mma_bf16(acc2[0], a2, b3 + 0);
                mma_bf16(acc2[1], a2, b3 + 2);
            }

            if (ch < 7) {
                CP_WAIT0();
                __syncthreads();
            }
        }

        __syncthreads();
        {
            float* D = (float*)(smem + SM_D);
            int r0 = (kh << 7) + 16 * wl + (lid >> 2);
            int cc = 2 * (lid & 3);
            #pragma unroll
            for (int nt = 0; nt < 4; nt++) {
                int col = 8 * nt + cc;
                *(float2*)&D[r0 * DPAD + col]       = make_float2(acc1[nt][0], acc1[nt][1]);
                *(float2*)&D[(r0 + 8) * DPAD + col] = make_float2(acc1[nt][2], acc1[nt][3]);
            }
            int r2 = 256 + (kh << 6) + 16 * (wl & 3) + (lid >> 2);
            int cb = ((wl >> 2) << 4) + cc;
            #pragma unroll
            for (int nt = 0; nt < 2; nt++) {
                int col = cb + 8 * nt;
                *(float2*)&D[r2 * DPAD + col]       = make_float2(acc2[nt][0], acc2[nt][1]);
                *(float2*)&D[(r2 + 8) * DPAD + col] = make_float2(acc2[nt][2], acc2[nt][3]);
            }
        }
        __syncthreads();

        {
            const float* D = (const float*)(smem + SM_D);
            const int b = b_epi;
            const int c0 = 4 * q_epi;
            float4 d0 = *(const float4*)&D[b * DPAD + c0];
            float4 d1 = *(const float4*)&D[(128 + b) * DPAD + c0];
            float4 d2 = *(const float4*)&D[(64 + b) * DPAD + c0];
            float4 d3 = *(const float4*)&D[(192 + b) * DPAD + c0];
            float4 d4 = *(const float4*)&D[(256 + b) * DPAD + c0];
            float4 d5 = *(const float4*)&D[(320 + b) * DPAD + c0];
            float pf = d0.x + d1.x + d2.x + d3.x + d4.x + d5.x + gxv.x;
            float pi = d0.y + d1.y + d2.y + d3.y + d4.y + d5.y + gxv.y;
            float pg = d0.z + d1.z + d2.z + d3.z + d4.z + d5.z + gxv.z;
            float po = d0.w + d1.w + d2.w + d3.w + d4.w + d5.w + gxv.w;

            float f = sigmoidf_(pf);
            float i = sigmoidf_(pi);
            float g = tanhf(pg);
            float o = sigmoidf_(po);
            float cc = f * c_state + i * g;
            float h = o * tanhf(cc);
            c_state = cc;

            __nv_bfloat16 hb = __float2bfloat16(h);
            float hf = __bfloat162float(hb);
            __nv_bfloat16 lb = __float2bfloat16(h - hf);

            int jg = blk * JPB + q_epi;
            int hoff = b * HID + jg;
            g_hhi[(t + 1) & 1][hoff] = *(unsigned short*)&hb;
            g_hlo[(t + 1) & 1][hoff] = *(unsigned short*)&lb;
            out[(size_t)t * (BATCH * HID) + hoff] = h;
            if (write_tail && t == T_STEPS - 1) {
                out[OUT_MAIN + hoff] = h;
                out[OUT_MAIN + BATCH * HID + hoff] = cc;
            }
        }

        __threadfence();
        __syncthreads();
        if (tid == 0) {
            atomicAdd(&g_sync, 1u);
            unsigned target = (unsigned)GRID_P * (unsigned)(t + 1);
            while (*(volatile unsigned*)&g_sync < target) { }
            __threadfence();
        }
        __syncthreads();
    }
}

// ---------------------------------------------------------------------------
extern "C" void kernel_launch(void* const* d_in, const int* in_sizes, int n_in,
                              void* d_out, int out_size) {
    const float* X  = (const float*)d_in[0];
    const float* Wf = (const float*)d_in[1];
    const float* bf = (const float*)d_in[2];
    const float* Wi = (const float*)d_in[3];
    const float* bi = (const float*)d_in[4];
    const float* Wg = (const float*)d_in[5];
    const float* bg = (const float*)d_in[6];
    const float* Wo = (const float*)d_in[7];
    const float* bo = (const float*)d_in[8];
    float* out = (float*)d_out;

    cudaFuncSetAttribute(lstm_persistent,
                         cudaFuncAttributeMaxDynamicSharedMemorySize, SMEM_TOTAL);
    cudaFuncSetAttribute(gemm_x_mma,
                         cudaFuncAttributeMaxDynamicSharedMemorySize, GX_SMEM);

    init_kernel<<<(BATCH * HID + 255) / 256, 256>>>(bf, bi, bg, bo);
    pack_kernel<<<dim3((DH - DIN) / 32, NG / 32), dim3(32, 32)>>>(Wf, Wi, Wg, Wo);
    wxpack_kernel<<<(NG * DIN / 4 + 255) / 256, 256>>>(Wf, Wi, Wg, Wo);
    xsplit_kernel<<<(M1 * DIN / 4 + 255) / 256, 256>>>(X);
    gemm_x_mma<<<dim3(NG / 64, M1 / 128), 256, GX_SMEM>>>(0);

    const long long OUT_MAIN = (long long)T_STEPS * BATCH * HID;
    int write_tail = ((long long)out_size >= OUT_MAIN + 2LL * BATCH * HID) ? 1 : 0;

    lstm_persistent<<<GRID_P, THR_P, SMEM_TOTAL>>>(out, write_tail);
}

// round 8
// speedup vs baseline: 3.3085x; 1.0314x over previous
#include <cuda_runtime.h>
#include <cuda_bf16.h>
#include <math.h>

// Problem constants
#define T_STEPS 256
#define BATCH   64
#define DIN     512
#define HID     1024
#define DH      (DIN + HID)       // 1536
#define NG      (4 * HID)         // 4096
#define M1      (T_STEPS * BATCH) // 16384

#define GRID_P  128               // persistent blocks
#define THR_R   256               // 8 warps (recurrence)
#define JPB     8                 // j-units per block
#define CPB     32                // gate-columns per block

// ---- LSTM SMEM layout (bytes) ------------------------------------------------
#define WPAD     1032
#define SM_WHI   0
#define SM_WLO   66048
#define APAD     136
#define SM_A0    132096
#define SM_A1    166912
#define SMEM_TOTAL 201728
#define SM_D     SM_A0
#define DPAD     36

// ---- gemm_x_mma SMEM layout --------------------------------------------------
#define GX_RS    72
#define GX_AHI   0
#define GX_ALO   18432
#define GX_BHI   36864
#define GX_BLO   46080
#define GX_BUF   55296
#define GX_SMEM  110592

// -------- device scratch -----------------------------------------------------
__device__ float g_Whp[(size_t)HID * NG];
__device__ float g_ball[NG];
__device__ float g_Gx[(size_t)M1 * NG];
__device__ unsigned short g_Xhi[(size_t)M1 * DIN];
__device__ unsigned short g_Xlo[(size_t)M1 * DIN];
__device__ unsigned short g_Wxhi[(size_t)NG * DIN];
__device__ unsigned short g_Wxlo[(size_t)NG * DIN];
__device__ unsigned short g_hhi[2][BATCH * HID];
__device__ unsigned short g_hlo[2][BATCH * HID];
__device__ unsigned g_sync;

// ---- helpers ------------------------------------------------------------
__device__ __forceinline__ unsigned smem_u32(const void* p) {
    unsigned a;
    asm("{ .reg .u64 t; cvta.to.shared.u64 t, %1; cvt.u32.u64 %0, t; }" : "=r"(a) : "l"(p));
    return a;
}
__device__ __forceinline__ void ldsm4(unsigned* r, unsigned addr) {
    asm volatile("ldmatrix.sync.aligned.m8n8.x4.shared.b16 {%0,%1,%2,%3}, [%4];"
        : "=r"(r[0]), "=r"(r[1]), "=r"(r[2]), "=r"(r[3]) : "r"(addr));
}
__device__ __forceinline__ void mma_bf16(float* d, const unsigned* a, const unsigned* b) {
    asm volatile("mma.sync.aligned.m16n8k16.row.col.f32.bf16.bf16.f32 "
        "{%0,%1,%2,%3}, {%4,%5,%6,%7}, {%8,%9}, {%0,%1,%2,%3};"
        : "+f"(d[0]), "+f"(d[1]), "+f"(d[2]), "+f"(d[3])
        : "r"(a[0]), "r"(a[1]), "r"(a[2]), "r"(a[3]), "r"(b[0]), "r"(b[1]));
}
__device__ __forceinline__ void cp16(unsigned dst, const void* src) {
    asm volatile("cp.async.cg.shared.global [%0], [%1], 16;" :: "r"(dst), "l"(src));
}
#define CP_COMMIT() asm volatile("cp.async.commit_group;" ::: "memory")
#define CP_WAIT0()  asm volatile("cp.async.wait_group 0;" ::: "memory")

__device__ __forceinline__ void split2(float x, float y, unsigned& hi, unsigned& lo) {
    unsigned h;
    asm("cvt.rn.bf16x2.f32 %0, %1, %2;" : "=r"(h) : "f"(y), "f"(x));
    float hx = __uint_as_float(h << 16);
    float hy = __uint_as_float(h & 0xffff0000u);
    float lx = x - hx, ly = y - hy;
    asm("cvt.rn.bf16x2.f32 %0, %1, %2;" : "=r"(lo) : "f"(ly), "f"(lx));
    hi = h;
}
__device__ __forceinline__ float sigmoidf_(float x) { return 1.0f / (1.0f + expf(-x)); }

// ---------------------------------------------------------------------------
__global__ void init_kernel(const float* __restrict__ bf, const float* __restrict__ bi,
                            const float* __restrict__ bg, const float* __restrict__ bo) {
    int idx = blockIdx.x * blockDim.x + threadIdx.x;
    if (idx < BATCH * HID) {
        g_hhi[0][idx] = 0; g_hhi[1][idx] = 0;
        g_hlo[0][idx] = 0; g_hlo[1][idx] = 0;
    }
    if (idx < NG) {
        int gate = idx >> 10;
        int j = idx & (HID - 1);
        const float* b = (gate == 0) ? bf : (gate == 1) ? bi : (gate == 2) ? bg : bo;
        g_ball[idx] = b[j];
    }
    if (idx == 0) g_sync = 0u;
}

__global__ void pack_kernel(const float* __restrict__ Wf, const float* __restrict__ Wi,
                            const float* __restrict__ Wg, const float* __restrict__ Wo) {
    __shared__ float tile[32][33];
    int tx = threadIdx.x, ty = threadIdx.y;
    int k0 = DIN + blockIdx.x * 32;
    int n0 = blockIdx.y * 32;
    int gate = n0 >> 10;
    const float* W = (gate == 0) ? Wf : (gate == 1) ? Wi : (gate == 2) ? Wg : Wo;
    int j0 = n0 & (HID - 1);

    tile[ty][tx] = W[(size_t)(j0 + ty) * DH + (k0 + tx)];
    __syncthreads();

    int k = k0 + ty;
    int n = n0 + tx;
    float v = tile[tx][ty];
    int kk = k - DIN;
    int j = n & (HID - 1);
    int g = n >> 10;
    int blk = j >> 3;
    int c = (j & 7) * 4 + g;
    g_Whp[((size_t)blk * CPB + c) * HID + kk] = v;
}

__global__ void wxpack_kernel(const float* __restrict__ Wf, const float* __restrict__ Wi,
                              const float* __restrict__ Wg, const float* __restrict__ Wo) {
    int i4 = blockIdx.x * blockDim.x + threadIdx.x;
    if (i4 >= NG * DIN / 4) return;
    int n = i4 >> 7;
    int k = (i4 & 127) << 2;
    int gate = n >> 10;
    int j = n & (HID - 1);
    const float* W = (gate == 0) ? Wf : (gate == 1) ? Wi : (gate == 2) ? Wg : Wo;
    float4 v = *(const float4*)(W + (size_t)j * DH + k);
    unsigned h01, l01, h23, l23;
    split2(v.x, v.y, h01, l01);
    split2(v.z, v.w, h23, l23);
    *(uint2*)&g_Wxhi[(size_t)n * DIN + k] = make_uint2(h01, h23);
    *(uint2*)&g_Wxlo[(size_t)n * DIN + k] = make_uint2(l01, l23);
}

__global__ void xsplit_kernel(const float* __restrict__ X) {
    int i4 = blockIdx.x * blockDim.x + threadIdx.x;
    if (i4 >= M1 * DIN / 4) return;
    size_t e = (size_t)i4 << 2;
    float4 v = *(const float4*)(X + e);
    unsigned h01, l01, h23, l23;
    split2(v.x, v.y, h01, l01);
    split2(v.z, v.w, h23, l23);
    *(uint2*)&g_Xhi[e] = make_uint2(h01, h23);
    *(uint2*)&g_Xlo[e] = make_uint2(l01, l23);
}

// ---------------------------------------------------------------------------
// gemm_x_mma (validated R7, unchanged)
// ---------------------------------------------------------------------------
__global__ void __launch_bounds__(256) gemm_x_mma(int dummy) {
    extern __shared__ char smem[];
    const unsigned sbase = smem_u32(smem);
    const int tid = threadIdx.x;
    const int w   = tid >> 5;
    const int lid = tid & 31;
    const int n0  = blockIdx.x * 64;
    const int m0  = blockIdx.y * 128;
    const int gate = n0 >> 10;
    const int jb   = n0 & (HID - 1);

    const unsigned a_off = (unsigned)((16 * w + (lid & 15)) * GX_RS + ((lid >> 4) << 3)) * 2;
    const unsigned b_off = (unsigned)((((lid >> 4) << 3) | (lid & 7)) * GX_RS
                                      + (((lid >> 3) & 1) << 3)) * 2;

    float acc[8][4];
    #pragma unroll
    for (int nt = 0; nt < 8; nt++)
        #pragma unroll
        for (int r = 0; r < 4; r++) acc[nt][r] = 0.f;

    const int st_c8 = (tid & 7) << 3;

    {
        const int k0 = 0;
        #pragma unroll
        for (int it = 0; it < 4; it++) {
            int row = (it << 5) + (tid >> 3);
            cp16(sbase + GX_AHI + (unsigned)(row * GX_RS + st_c8) * 2,
                 g_Xhi + (size_t)(m0 + row) * DIN + k0 + st_c8);
            cp16(sbase + GX_ALO + (unsigned)(row * GX_RS + st_c8) * 2,
                 g_Xlo + (size_t)(m0 + row) * DIN + k0 + st_c8);
        }
        #pragma unroll
        for (int it = 0; it < 2; it++) {
            int row = (it << 5) + (tid >> 3);
            cp16(sbase + GX_BHI + (unsigned)(row * GX_RS + st_c8) * 2,
                 g_Wxhi + (size_t)(n0 + row) * DIN + k0 + st_c8);
            cp16(sbase + GX_BLO + (unsigned)(row * GX_RS + st_c8) * 2,
                 g_Wxlo + (size_t)(n0 + row) * DIN + k0 + st_c8);
        }
        CP_COMMIT();
        CP_WAIT0();
        __syncthreads();
    }

    for (int ch = 0; ch < 8; ch++) {
        const unsigned buf = sbase + (ch & 1) * GX_BUF;
        if (ch < 7) {
            const int k0 = (ch + 1) << 6;
            const unsigned dbuf = sbase + ((ch + 1) & 1) * GX_BUF;
            #pragma unroll
            for (int it = 0; it < 4; it++) {
                int row = (it << 5) + (tid >> 3);
                cp16(dbuf + GX_AHI + (unsigned)(row * GX_RS + st_c8) * 2,
                     g_Xhi + (size_t)(m0 + row) * DIN + k0 + st_c8);
                cp16(dbuf + GX_ALO + (unsigned)(row * GX_RS + st_c8) * 2,
                     g_Xlo + (size_t)(m0 + row) * DIN + k0 + st_c8);
            }
            #pragma unroll
            for (int it = 0; it < 2; it++) {
                int row = (it << 5) + (tid >> 3);
                cp16(dbuf + GX_BHI + (unsigned)(row * GX_RS + st_c8) * 2,
                     g_Wxhi + (size_t)(n0 + row) * DIN + k0 + st_c8);
                cp16(dbuf + GX_BLO + (unsigned)(row * GX_RS + st_c8) * 2,
                     g_Wxlo + (size_t)(n0 + row) * DIN + k0 + st_c8);
            }
            CP_COMMIT();
        }

        #pragma unroll
        for (int kk = 0; kk < 4; kk++) {
            const unsigned ko = (unsigned)(kk << 5);
            unsigned ahi[4], alo[4];
            ldsm4(ahi, buf + GX_AHI + a_off + ko);
            ldsm4(alo, buf + GX_ALO + a_off + ko);
            #pragma unroll
            for (int s = 0; s < 4; s++) {
                const unsigned so = (unsigned)(s * 16 * GX_RS * 2);
                unsigned bhi[4], blo[4];
                ldsm4(bhi, buf + GX_BHI + b_off + so + ko);
                ldsm4(blo, buf + GX_BLO + b_off + so + ko);
                mma_bf16(acc[2 * s],     ahi, bhi + 0);
                mma_bf16(acc[2 * s],     alo, bhi + 0);
                mma_bf16(acc[2 * s],     ahi, blo + 0);
                mma_bf16(acc[2 * s],     alo, blo + 0);
                mma_bf16(acc[2 * s + 1], ahi, bhi + 2);
                mma_bf16(acc[2 * s + 1], alo, bhi + 2);
                mma_bf16(acc[2 * s + 1], ahi, blo + 2);
                mma_bf16(acc[2 * s + 1], alo, blo + 2);
            }
        }

        if (ch < 7) {
            CP_WAIT0();
            __syncthreads();
        }
    }

    const int r0 = m0 + 16 * w + (lid >> 2);
    #pragma unroll
    for (int nt = 0; nt < 8; nt++) {
        int jc = jb + nt * 8 + (lid & 3) * 2;
        float b0 = g_ball[(gate << 10) + jc];
        float b1 = g_ball[(gate << 10) + jc + 1];
        g_Gx[(size_t)r0 * NG + jc * 4 + gate]           = acc[nt][0] + b0;
        g_Gx[(size_t)r0 * NG + (jc + 1) * 4 + gate]     = acc[nt][1] + b1;
        g_Gx[(size_t)(r0 + 8) * NG + jc * 4 + gate]     = acc[nt][2] + b0;
        g_Gx[(size_t)(r0 + 8) * NG + (jc + 1) * 4 + gate] = acc[nt][3] + b1;
    }
}

// ---------------------------------------------------------------------------
// Persistent recurrence, retiled: 128 blocks x 256 threads (8 warps).
//   warp: kh = w>>2 (k-half), wl = w&3. Per k16: 6 ldsm -> 12 mma
//   (A' tiles {16wl, 64+16wl} x Whi[32], + hi tile x Wlo[32] reusing A regs).
// ---------------------------------------------------------------------------
__global__ void __launch_bounds__(THR_R, 1) lstm_persistent(float* __restrict__ out,
                                                            int write_tail) {
    extern __shared__ char smem[];
    const unsigned sbase = smem_u32(smem);
    const int tid = threadIdx.x;
    const int w   = tid >> 5;
    const int lid = tid & 31;
    const int kh  = w >> 2;            // 0: kk 0-3, 1: kk 4-7
    const int wl  = w & 3;
    const int blk = blockIdx.x;

    // ---- stage weights once: fp32 -> bf16 hi/lo, [c][WPAD] layout ----
    {
        const float* wsrc = g_Whp + (size_t)blk * CPB * HID;
        for (int i4 = tid; i4 < CPB * HID / 4; i4 += THR_R) {
            int c = i4 >> 8;
            int k = (i4 << 2) & 1023;
            float4 v = *(const float4*)(wsrc + ((size_t)c << 10) + k);
            unsigned h01, l01, h23, l23;
            split2(v.x, v.y, h01, l01);
            split2(v.z, v.w, h23, l23);
            unsigned off = (unsigned)(c * WPAD + k) * 2;
            *(uint2*)(smem + SM_WHI + off) = make_uint2(h01, h23);
            *(uint2*)(smem + SM_WLO + off) = make_uint2(l01, l23);
        }
    }
    __syncthreads();

    // ldsm lane addressing
    const unsigned a0_row = (unsigned)((16 * wl + (lid & 15)) * APAD + ((lid >> 4) << 3)) * 2;
    const unsigned A1OFF  = 64u * APAD * 2u;   // +64 rows
    const int c_i   = ((lid >> 4) << 3) + (lid & 7);
    const int khalf = ((lid >> 3) & 1) << 3;
    const unsigned bhi0 = sbase + SM_WHI + (unsigned)(c_i * WPAD + khalf) * 2;
    const unsigned bhi1 = sbase + SM_WHI + (unsigned)((16 + c_i) * WPAD + khalf) * 2;
    const unsigned blo0 = sbase + SM_WLO + (unsigned)(c_i * WPAD + khalf) * 2;
    const unsigned blo1 = sbase + SM_WLO + (unsigned)((16 + c_i) * WPAD + khalf) * 2;

    float c_state[2] = {0.f, 0.f};
    const int b_epi = tid >> 2;        // batch row 0..63
    const int q_epi = tid & 3;         // owns j-units 2q, 2q+1
    const long long OUT_MAIN = (long long)T_STEPS * BATCH * HID;

    for (int t = 0; t < T_STEPS; t++) {
        const unsigned short* hhi = g_hhi[t & 1];
        const unsigned short* hlo = g_hlo[t & 1];

        // prefetch Gx (DRAM latency hidden under staging+mma)
        const size_t gxbase = ((size_t)t * BATCH + b_epi) * NG + blk * CPB + 8 * q_epi;
        const float4 gxv0 = *(const float4*)&g_Gx[gxbase];
        const float4 gxv1 = *(const float4*)&g_Gx[gxbase + 4];

        // ---- stage chunk 0 (8 cp16/thread) ----
        {
            #pragma unroll
            for (int it = 0; it < 8; it++) {
                int slot = it * THR_R + tid;
                int part = slot >> 10;
                int row = (slot >> 4) & 63;
                int c8 = (slot & 15) << 3;
                const unsigned short* src = (part ? hlo : hhi) + row * HID + c8;
                unsigned dst = sbase + SM_A0 +
                    (unsigned)(((part << 6) + row) * APAD + c8) * 2;
                cp16(dst, src);
            }
            CP_COMMIT();
            CP_WAIT0();
            __syncthreads();
        }

        float acc1[2][4][4], acc2[4][4];
        #pragma unroll
        for (int tl = 0; tl < 2; tl++)
            #pragma unroll
            for (int n = 0; n < 4; n++)
                #pragma unroll
                for (int r = 0; r < 4; r++) acc1[tl][n][r] = 0.f;
        #pragma unroll
        for (int n = 0; n < 4; n++)
            #pragma unroll
            for (int r = 0; r < 4; r++) acc2[n][r] = 0.f;

        for (int ch = 0; ch < 8; ch++) {
            const unsigned abuf = sbase + ((ch & 1) ? SM_A1 : SM_A0);
            if (ch < 7) {
                const int k0n = (ch + 1) << 7;
                const unsigned dbase = sbase + (((ch + 1) & 1) ? SM_A1 : SM_A0);
                #pragma unroll
                for (int it = 0; it < 8; it++) {
                    int slot = it * THR_R + tid;
                    int part = slot >> 10;
                    int row = (slot >> 4) & 63;
                    int c8 = (slot & 15) << 3;
                    const unsigned short* src = (part ? hlo : hhi) + row * HID + k0n + c8;
                    unsigned dst = dbase +
                        (unsigned)(((part << 6) + row) * APAD + c8) * 2;
                    cp16(dst, src);
                }
                CP_COMMIT();
            }

            #pragma unroll
            for (int kkl = 0; kkl < 4; kkl++) {
                const int kk = (kh << 2) + kkl;
                const unsigned akoff = (unsigned)(kk << 5);
                const unsigned wkoff = (unsigned)(((ch << 7) + (kk << 4)) << 1);
                unsigned a0[4], a1[4], bh0[4], bh1[4], bl0[4], bl1[4];
                ldsm4(a0, abuf + a0_row + akoff);
                ldsm4(bh0, bhi0 + wkoff);
                ldsm4(bh1, bhi1 + wkoff);
                ldsm4(a1, abuf + a0_row + A1OFF + akoff);
                ldsm4(bl0, blo0 + wkoff);
                ldsm4(bl1, blo1 + wkoff);
                // acc1 tile0 (A' hi rows) x Whi
                mma_bf16(acc1[0][0], a0, bh0 + 0);
                mma_bf16(acc1[0][1], a0, bh0 + 2);
                mma_bf16(acc1[0][2], a0, bh1 + 0);
                mma_bf16(acc1[0][3], a0, bh1 + 2);
                // acc1 tile1 (A' lo rows) x Whi
                mma_bf16(acc1[1][0], a1, bh0 + 0);
                mma_bf16(acc1[1][1], a1, bh0 + 2);
                mma_bf16(acc1[1][2], a1, bh1 + 0);
                mma_bf16(acc1[1][3], a1, bh1 + 2);
                // acc2 (hi rows, reuse a0) x Wlo
                mma_bf16(acc2[0], a0, bl0 + 0);
                mma_bf16(acc2[1], a0, bl0 + 2);
                mma_bf16(acc2[2], a0, bl1 + 0);
                mma_bf16(acc2[3], a0, bl1 + 2);
            }

            if (ch < 7) {
                CP_WAIT0();
                __syncthreads();
            }
        }

        // ---- exchange accumulators (same layout/epilogue semantics as R6) ----
        __syncthreads();
        {
            float* D = (float*)(smem + SM_D);
            int rr = lid >> 2;
            int cc = 2 * (lid & 3);
            int r_t0 = (kh << 7) + 16 * wl + rr;            // A' hi rows
            int r_t1 = (kh << 7) + 64 + 16 * wl + rr;       // A' lo rows
            int r_a2 = 256 + (kh << 6) + 16 * wl + rr;      // acc2 rows
            #pragma unroll
            for (int nt = 0; nt < 4; nt++) {
                int col = 8 * nt + cc;
                *(float2*)&D[r_t0 * DPAD + col]       = make_float2(acc1[0][nt][0], acc1[0][nt][1]);
                *(float2*)&D[(r_t0 + 8) * DPAD + col] = make_float2(acc1[0][nt][2], acc1[0][nt][3]);
                *(float2*)&D[r_t1 * DPAD + col]       = make_float2(acc1[1][nt][0], acc1[1][nt][1]);
                *(float2*)&D[(r_t1 + 8) * DPAD + col] = make_float2(acc1[1][nt][2], acc1[1][nt][3]);
                *(float2*)&D[r_a2 * DPAD + col]       = make_float2(acc2[nt][0], acc2[nt][1]);
                *(float2*)&D[(r_a2 + 8) * DPAD + col] = make_float2(acc2[nt][2], acc2[nt][3]);
            }
        }
        __syncthreads();

        // ---- fused epilogue: thread owns (b, 2 j-units) ----
        float hout[2];
        {
            const float* D = (const float*)(smem + SM_D);
            const int b = b_epi;
            #pragma unroll
            for (int u = 0; u < 2; u++) {
                int c0 = 8 * q_epi + 4 * u;
                float4 d0 = *(const float4*)&D[b * DPAD + c0];
                float4 d1 = *(const float4*)&D[(128 + b) * DPAD + c0];
                float4 d2 = *(const float4*)&D[(64 + b) * DPAD + c0];
                float4 d3 = *(const float4*)&D[(192 + b) * DPAD + c0];
                float4 d4 = *(const float4*)&D[(256 + b) * DPAD + c0];
                float4 d5 = *(const float4*)&D[(320 + b) * DPAD + c0];
                float4 gv = u ? gxv1 : gxv0;
                float pf = d0.x + d1.x + d2.x + d3.x + d4.x + d5.x + gv.x;
                float pi = d0.y + d1.y + d2.y + d3.y + d4.y + d5.y + gv.y;
                float pg = d0.z + d1.z + d2.z + d3.z + d4.z + d5.z + gv.z;
                float po = d0.w + d1.w + d2.w + d3.w + d4.w + d5.w + gv.w;
                float f = sigmoidf_(pf);
                float i = sigmoidf_(pi);
                float g = tanhf(pg);
                float o = sigmoidf_(po);
                float cc = f * c_state[u] + i * g;
                hout[u] = o * tanhf(cc);
                c_state[u] = cc;
            }
        }
        unsigned hi2, lo2;
        split2(hout[0], hout[1], hi2, lo2);
        const int jg0 = blk * JPB + 2 * q_epi;
        const int hoff = b_epi * HID + jg0;
        *(unsigned*)&g_hhi[(t + 1) & 1][hoff] = hi2;
        *(unsigned*)&g_hlo[(t + 1) & 1][hoff] = lo2;

        // ---- grid barrier: arrive, overlap out-store with polling ----
        __threadfence();
        __syncthreads();
        if (tid == 0) atomicAdd(&g_sync, 1u);
        *(float2*)&out[(size_t)t * (BATCH * HID) + hoff] = make_float2(hout[0], hout[1]);
        if (write_tail && t == T_STEPS - 1) {
            *(float2*)&out[OUT_MAIN + hoff] = make_float2(hout[0], hout[1]);
            *(float2*)&out[OUT_MAIN + BATCH * HID + hoff] = make_float2(c_state[0], c_state[1]);
        }
        if (tid == 0) {
            unsigned target = (unsigned)GRID_P * (unsigned)(t + 1);
            while (*(volatile unsigned*)&g_sync < target) { }
            __threadfence();
        }
        __syncthreads();
    }
}

// ---------------------------------------------------------------------------
extern "C" void kernel_launch(void* const* d_in, const int* in_sizes, int n_in,
                              void* d_out, int out_size) {
    const float* X  = (const float*)d_in[0];
    const float* Wf = (const float*)d_in[1];
    const float* bf = (const float*)d_in[2];
    const float* Wi = (const float*)d_in[3];
    const float* bi = (const float*)d_in[4];
    const float* Wg = (const float*)d_in[5];
    const float* bg = (const float*)d_in[6];
    const float* Wo = (const float*)d_in[7];
    const float* bo = (const float*)d_in[8];
    float* out = (float*)d_out;

    cudaFuncSetAttribute(lstm_persistent,
                         cudaFuncAttributeMaxDynamicSharedMemorySize, SMEM_TOTAL);
    cudaFuncSetAttribute(gemm_x_mma,
                         cudaFuncAttributeMaxDynamicSharedMemorySize, GX_SMEM);

    init_kernel<<<(BATCH * HID + 255) / 256, 256>>>(bf, bi, bg, bo);
    pack_kernel<<<dim3((DH - DIN) / 32, NG / 32), dim3(32, 32)>>>(Wf, Wi, Wg, Wo);
    wxpack_kernel<<<(NG * DIN / 4 + 255) / 256, 256>>>(Wf, Wi, Wg, Wo);
    xsplit_kernel<<<(M1 * DIN / 4 + 255) / 256, 256>>>(X);
    gemm_x_mma<<<dim3(NG / 64, M1 / 128), 256, GX_SMEM>>>(0);

    const long long OUT_MAIN = (long long)T_STEPS * BATCH * HID;
    int write_tail = ((long long)out_size >= OUT_MAIN + 2LL * BATCH * HID) ? 1 : 0;

    lstm_persistent<<<GRID_P, THR_R, SMEM_TOTAL>>>(out, write_tail);
}